// round 14
// baseline (speedup 1.0000x reference)
#include <cuda_runtime.h>
#include <math.h>

#define Bn 16
#define Nn 256
#define Tn 64
#define Wn 12
#define Hn 64
#define EDn 64
#define Sn 5
#define Cn 4
#define En 2048
#define FGn 76   // W + H
#define CAP 64
#define GBLK 9            // blocks per batch group
#define NBLK (Bn * GBLK)  // 144
#define NT 512            // threads per block

typedef unsigned long long ull;

// ---------------- f32x2 packed-FMA helpers (sm_103a FFMA2) ----------------
__device__ __forceinline__ void fma2(ull& d, ull a, ull b) {
    asm("fma.rn.f32x2 %0, %1, %2, %0;" : "+l"(d) : "l"(a), "l"(b));
}
__device__ __forceinline__ ull splat2(float v) {
    ull r; asm("mov.b64 %0, {%1, %1};" : "=l"(r) : "f"(v)); return r;
}
__device__ __forceinline__ ull pack2(float lo, float hi) {
    ull r; asm("mov.b64 %0, {%1, %2};" : "=l"(r) : "f"(lo), "f"(hi)); return r;
}
__device__ __forceinline__ float2 unpack2(ull v) {
    float lo, hi; asm("mov.b64 {%0, %1}, %2;" : "=f"(lo), "=f"(hi) : "l"(v));
    return make_float2(lo, hi);
}
__device__ __forceinline__ float hadd2(ull v) { float2 f = unpack2(v); return f.x + f.y; }

// triangular pair LUT (36 pairs of 8x8 tiles), role r owns pairs 4r..4r+3
__device__ __constant__ signed char c_iT[36] =
    {0,0,0,0,0,0,0,0, 1,1,1,1,1,1,1, 2,2,2,2,2,2, 3,3,3,3,3, 4,4,4,4, 5,5,5, 6,6, 7};
__device__ __constant__ signed char c_jT[36] =
    {0,1,2,3,4,5,6,7, 1,2,3,4,5,6,7, 2,3,4,5,6,7, 3,4,5,6,7, 4,5,6,7, 5,6,7, 6,7, 7};
// per-role distinct row-tile lists + per-pair slot indices into the list
__device__ __constant__ signed char c_nload[9] = {4,5,4,5,5,5,5,4,3};
__device__ __constant__ signed char c_tiles[9][5] = {
    {0,1,2,3,0}, {0,4,5,6,7}, {1,2,3,4,0}, {1,5,6,7,2}, {2,3,4,5,6},
    {2,7,3,4,5}, {3,6,7,4,5}, {4,6,7,5,0}, {5,7,6,0,0}};
__device__ __constant__ signed char c_pi[9][4] = {
    {0,0,0,0}, {0,0,0,0}, {0,0,0,0}, {0,0,0,4}, {0,0,0,0},
    {0,2,2,2}, {0,0,3,3}, {0,0,3,3}, {0,2,2,1}};
__device__ __constant__ signed char c_pj[9][4] = {
    {0,1,2,3}, {1,2,3,4}, {0,1,2,3}, {1,2,3,4}, {1,2,3,4},
    {1,2,3,4}, {1,2,3,4}, {1,2,3,1}, {1,2,1,1}};

// ---------------- device scratch ----------------
__device__ float g_dinv_stat[Nn];
__device__ int   g_nbr_cnt[Nn];
__device__ int   g_nbr_idx[Nn * CAP];
__device__ float g_nbr_w[Nn * CAP];
__device__ float g_coef[6 * Hn];
__device__ float g_XW[Bn * Nn * EDn];
__device__ float g_de1[Bn * Nn * EDn];
__device__ float g_de2[Bn * Nn * EDn];
__device__ float g_Eh[(size_t)Bn * Sn * Nn * Nn];
__device__ float g_Msum[(size_t)Bn * Nn * Nn];
__device__ float g_colsum[Bn * Nn];
__device__ float g_h[Bn * Nn * Hn];
__device__ unsigned g_bcount[Bn * 32];
__device__ unsigned g_bgen[Bn * 32];

// ---------------- smem layout (floats) ----------------
#define OFF_W1   0
#define OFF_W2   4096
#define OFF_WZ   8192
#define OFF_WR   12288
#define OFF_WH   16384
#define OFF_WG   20480          // 4864
#define OFF_COEF 25344          // 384
#define OFF_BIAS 25728          // 384: [b1,b2,bz,br,bh,gconv_b]
#define OFF_H    26112          // 2048 persistent h rows
#define OFF_NBRW 28160          // 2048
#define OFF_NBRI 30208          // 2048 (int view)
#define OFF_NBRC 32256          // 32 (int view)
#define OFF_WK   32288
// phase B: 5 tile slots x (de1,de2) x 32x68  + 4 colbufs of 64
#define DSLOT    4352           // 2 * 2176
#define OFF_CB   (OFF_WK + 5 * DSLOT)   // +21760
#define SMEM_FLOATS (OFF_CB + 256)
#define SMEM_BYTES (SMEM_FLOATS * 4)

// ---------------- per-batch grid barrier (9 arrivals) ----------------
__device__ __forceinline__ void gsync_b(int grp, unsigned& lgen) {
    __syncthreads();
    if (threadIdx.x == 0) {
        unsigned* cnt = &g_bcount[grp * 32];
        unsigned* gen = &g_bgen[grp * 32];
        __threadfence();
        if (atomicAdd(cnt, 1u) == (unsigned)(GBLK - 1)) {
            *cnt = 0u;
            __threadfence();
            atomicAdd(gen, 1u);
        } else {
            while (atomicAdd(gen, 0u) <= lgen) { __nanosleep(20); }
        }
        __threadfence();
    }
    lgen++;
    __syncthreads();
}

// ---------------- setup kernels ----------------
__global__ void k_zero() {
    size_t idx = (size_t)blockIdx.x * blockDim.x + threadIdx.x;
    size_t str = (size_t)gridDim.x * blockDim.x;
    if (idx < Bn * 32) { g_bcount[idx] = 0u; g_bgen[idx] = 0u; }
    for (size_t i = idx; i < (size_t)Bn * Sn * Nn * Nn; i += str) g_Eh[i] = 0.f;
    for (size_t i = idx; i < (size_t)Bn * Nn * Nn; i += str) g_Msum[i] = 0.f;
    for (size_t i = idx; i < (size_t)Bn * Nn; i += str) g_colsum[i] = 0.f;
}

__global__ void k_build(const int* __restrict__ ei, const float* __restrict__ ew) {
    int j = threadIdx.x;  // 256 threads, 1 block
    float deg = 1.0f;
    for (int e = 0; e < En; e++)
        if (ei[En + e] == j) deg += ew[e];
    g_dinv_stat[j] = 1.0f / sqrtf(deg);
    __syncthreads();
    float dj = g_dinv_stat[j];
    int cnt = 1;
    g_nbr_idx[j * CAP] = j;
    g_nbr_w[j * CAP] = dj * dj;
    for (int e = 0; e < En; e++) {
        if (ei[En + e] == j && cnt < CAP) {
            int s = ei[e];
            g_nbr_idx[j * CAP + cnt] = s;
            g_nbr_w[j * CAP + cnt] = g_dinv_stat[s] * ew[e] * dj;
            cnt++;
        }
    }
    g_nbr_cnt[j] = cnt;
}

__global__ void k_precoef(const float* wz_c, const float* wz_l, const float* bz_c,
                          const float* wr_c, const float* wr_l, const float* br_c,
                          const float* wh_c, const float* wh_l, const float* bh_c) {
    int k = threadIdx.x;  // 64 threads
    float az = 0, cz = 0, ar = 0, cr = 0, ah = 0, ch = 0;
    for (int f = 0; f < Hn; f++) {
        float wzl = wz_l[f * Hn + k], wrl = wr_l[f * Hn + k], whl = wh_l[f * Hn + k];
        az += wz_c[f] * wzl;  cz += bz_c[f] * wzl;
        ar += wr_c[f] * wrl;  cr += br_c[f] * wrl;
        ah += wh_c[f] * whl;  ch += bh_c[f] * whl;
    }
    g_coef[k] = az;        g_coef[64 + k] = cz;
    g_coef[128 + k] = ar;  g_coef[192 + k] = cr;
    g_coef[256 + k] = ah;  g_coef[320 + k] = ch;
}

// ---------------- persistent kernel: whole T-step scan ----------------
__global__ __launch_bounds__(NT, 1) void k_persist(
    const float* __restrict__ x, const float* __restrict__ Wg,
    const float* __restrict__ gconv_b,
    const float* __restrict__ w1, const float* __restrict__ b1,
    const float* __restrict__ w2, const float* __restrict__ b2,
    const float* __restrict__ bz_lf, const float* __restrict__ wz_l,
    const float* __restrict__ br_lf, const float* __restrict__ wr_l,
    const float* __restrict__ bh_lf, const float* __restrict__ wh_l)
{
    extern __shared__ float sm[];
    int tid = threadIdx.x, bid = blockIdx.x;
    int grp = bid / GBLK;          // batch
    int role = bid - grp * GBLK;   // 0..8
    int bA = grp, nT = role;
    bool ac_on = (role < 8);
    unsigned lgen = 0;

    float* sW1 = sm + OFF_W1;
    float* sW2 = sm + OFF_W2;
    float* sWz = sm + OFF_WZ;
    float* sWr = sm + OFF_WR;
    float* sWh = sm + OFF_WH;
    float* sWg = sm + OFF_WG;
    float* sCoef = sm + OFF_COEF;
    float* sBias = sm + OFF_BIAS;
    float* hS = sm + OFF_H;
    float* sNbrW = sm + OFF_NBRW;
    int* sNbrI = (int*)(sm + OFF_NBRI);
    int* sNbrC = (int*)(sm + OFF_NBRC);
    float* wk = sm + OFF_WK;
    float* cb = sm + OFF_CB;

    // ---- load all weights once ----
    for (int i = tid; i < 4096; i += NT) {
        sW1[i] = w1[i];
        sW2[i] = w2[i];
        int r = i >> 6, c = i & 63;
        sWz[i] = wz_l[(64 + r) * 64 + c];
        sWr[i] = wr_l[(64 + r) * 64 + c];
        sWh[i] = wh_l[(64 + r) * 64 + c];
    }
    for (int i = tid; i < FGn * 64; i += NT) sWg[i] = Wg[i];
    for (int i = tid; i < 384; i += NT) sCoef[i] = g_coef[i];
    if (tid < 64) {
        sBias[tid] = b1[tid];        sBias[64 + tid] = b2[tid];
        sBias[128 + tid] = bz_lf[tid]; sBias[192 + tid] = br_lf[tid];
        sBias[256 + tid] = bh_lf[tid]; sBias[320 + tid] = gconv_b[tid];
    }
    for (int i = tid; i < 2048; i += NT) hS[i] = 0.f;

    if (ac_on) {
        for (int i = tid; i < 32 * CAP; i += NT) {
            sNbrI[i] = g_nbr_idx[nT * 32 * CAP + i];
            sNbrW[i] = g_nbr_w[nT * 32 * CAP + i];
        }
        if (tid < 32) sNbrC[tid] = g_nbr_cnt[nT * 32 + tid];
    }
    __syncthreads();

    int tx = tid & 31, ty = tid >> 5;   // ty 0..15
    int f0 = tx * 2, r0 = ty * 2;       // 2-row register tiles (phases A/C)

    // phase B decomposition: 4 groups of 128 threads, one tile pair each
    int pg = tid >> 7;                  // 0..3
    int gt = tid & 127;
    int btx = gt & 7, bty = gt >> 3;    // 8 x 16 thread grid per group

    // ---- initial XW (t=0, h=0) ----
    if (ac_on) {
        float* sIt = wk;  // [32][12]
        for (int i = tid; i < 384; i += NT) {
            int rr = i / 12, c = i - rr * 12;
            int tt = c - (Wn - 1);
            sIt[i] = (tt >= 0) ? x[(bA * Nn + nT * 32 + rr) * Tn + tt] : 0.f;
        }
        __syncthreads();
        ull acc[2] = {0ull, 0ull};
#pragma unroll
        for (int c = 0; c < Wn; c++) {
            ull wv = *(const ull*)&sWg[c * 64 + f0];
#pragma unroll
            for (int jy = 0; jy < 2; jy++) fma2(acc[jy], splat2(sIt[(r0 + jy) * 12 + c]), wv);
        }
#pragma unroll
        for (int jy = 0; jy < 2; jy++)
            *(float2*)&g_XW[(bA * Nn + nT * 32 + r0 + jy) * EDn + f0] = unpack2(acc[jy]);
    }
    gsync_b(grp, lgen);

    for (int t = 0; t < Tn; t++) {
        int slot = t % Sn;
        float cnt = (float)((t + 1 < Sn) ? (t + 1) : Sn);

        // ================= phase A: df gather + de1/de2 =================
        if (ac_on) {
            float* dfS = wk;  // [32][64]
            {
                int f = tid & 63, jg = tid >> 6;   // jg 0..7
                float gb = sBias[320 + f];
#pragma unroll
                for (int q = 0; q < 4; q++) {
                    int jl = jg + q * 8;
                    int nc = sNbrC[jl];
                    float acc = 0.f;
                    for (int k = 0; k < nc; k++)
                        acc += sNbrW[jl * CAP + k] * g_XW[(bA * Nn + sNbrI[jl * CAP + k]) * EDn + f];
                    dfS[jl * 64 + f] = acc + gb;
                }
            }
            __syncthreads();
            ull a1[2], a2[2];
#pragma unroll
            for (int jy = 0; jy < 2; jy++) { a1[jy] = 0ull; a2[jy] = 0ull; }
#pragma unroll 4
            for (int ff = 0; ff < 64; ff += 4) {
                float4 D[2];
#pragma unroll
                for (int jy = 0; jy < 2; jy++) D[jy] = *(const float4*)&dfS[(r0 + jy) * 64 + ff];
                const float* Dp = (const float*)D;
#pragma unroll
                for (int s = 0; s < 4; s++) {
                    ull w1v = *(const ull*)&sW1[(ff + s) * 64 + f0];
                    ull w2v = *(const ull*)&sW2[(ff + s) * 64 + f0];
#pragma unroll
                    for (int jy = 0; jy < 2; jy++) {
                        ull dv = splat2(Dp[jy * 4 + s]);
                        fma2(a1[jy], dv, w1v);
                        fma2(a2[jy], dv, w2v);
                    }
                }
            }
            {
                float bb10 = sBias[f0], bb11 = sBias[f0 + 1];
                float bb20 = sBias[64 + f0], bb21 = sBias[64 + f0 + 1];
#pragma unroll
                for (int jy = 0; jy < 2; jy++) {
                    int row = (bA * Nn + nT * 32 + r0 + jy) * EDn;
                    float2 v1 = unpack2(a1[jy]);
                    float2 v2 = unpack2(a2[jy]);
                    *(float2*)&g_de1[row + f0] = make_float2(tanhf(v1.x + bb10), tanhf(v1.y + bb11));
                    *(float2*)&g_de2[row + f0] = make_float2(tanhf(v2.x + bb20), tanhf(v2.y + bb21));
                }
            }
        }
        gsync_b(grp, lgen);

        // ===== phase B: single pass — 4 concurrent pairs over a 5-tile shared pool =====
        {
            int nload = c_nload[role];
            // cooperative load of distinct tiles (de1, de2) into pool
            for (int u = tid; u < nload * 1024; u += NT) {
                int slot_ = u >> 10;
                int rem = u & 1023;
                int mat = rem >> 9;
                int w = rem & 511;
                int rr = w >> 4, e4 = (w & 15) << 2;
                int tile = c_tiles[role][slot_];
                const float* src = mat ? g_de2 : g_de1;
                *(float4*)&wk[slot_ * DSLOT + mat * 2176 + rr * 68 + e4] =
                    *(const float4*)&src[(bA * Nn + tile * 32 + rr) * EDn + e4];
            }
            if (tid < 256) cb[tid] = 0.f;
            __syncthreads();

            int u = role * 4 + pg;
            int iT = c_iT[u], jT = c_jT[u];
            bool diag = (iT == jT);
            const float* d1i = wk + c_pi[role][pg] * DSLOT;
            const float* d2i = d1i + 2176;
            const float* d1j = wk + c_pj[role][pg] * DSLOT;
            const float* d2j = d1j + 2176;
            float* cbg = cb + pg * 64;

            // 2x4 cells: rows {bty, bty+16}, cols {btx+8c}
            ull accA[2][4], accB[2][4];
#pragma unroll
            for (int a = 0; a < 2; a++)
#pragma unroll
                for (int c = 0; c < 4; c++) { accA[a][c] = 0ull; accB[a][c] = 0ull; }
#pragma unroll
            for (int e0 = 0; e0 < 64; e0 += 4) {
                ulonglong2 P1[2], P2[2];
#pragma unroll
                for (int a = 0; a < 2; a++) {
                    P1[a] = *(const ulonglong2*)&d1i[(bty + 16 * a) * 68 + e0];
                    P2[a] = *(const ulonglong2*)&d2i[(bty + 16 * a) * 68 + e0];
                }
#pragma unroll
                for (int c = 0; c < 4; c++) {
                    ulonglong2 Q1 = *(const ulonglong2*)&d1j[(btx + 8 * c) * 68 + e0];
                    ulonglong2 Q2 = *(const ulonglong2*)&d2j[(btx + 8 * c) * 68 + e0];
#pragma unroll
                    for (int a = 0; a < 2; a++) {
                        fma2(accA[a][c], P1[a].x, Q2.x);  fma2(accA[a][c], P1[a].y, Q2.y);
                        fma2(accB[a][c], Q1.x, P2[a].x);  fma2(accB[a][c], Q1.y, P2[a].y);
                    }
                }
            }
            float tv[2][4];
#pragma unroll
            for (int a = 0; a < 2; a++)
#pragma unroll
                for (int c = 0; c < 4; c++)
                    tv[a][c] = tanhf(hadd2(accA[a][c]) - hadd2(accB[a][c]));

            // register-direct RMW (normal tile), per-c column sums
            size_t ebase = ((size_t)(bA * Sn + slot) * Nn) * Nn;
            size_t mbase = ((size_t)bA * Nn) * Nn;
#pragma unroll
            for (int c = 0; c < 4; c++) {
                float csum = 0.f;
                int gj = jT * 32 + btx + 8 * c;
#pragma unroll
                for (int a = 0; a < 2; a++) {
                    int gi = iT * 32 + bty + 16 * a;
                    float et = fmaxf(tv[a][c], 0.f);
                    size_t eo = ebase + (size_t)gi * Nn + gj;
                    float old = g_Eh[eo];
                    g_Eh[eo] = et;
                    float d = et - old;
                    g_Msum[mbase + (size_t)gi * Nn + gj] += d;
                    csum += d;
                }
                atomicAdd(&cbg[btx + 8 * c], csum);
            }
            if (!diag) {
#pragma unroll
                for (int a = 0; a < 2; a++) {
                    float csum = 0.f;
                    int gj = iT * 32 + bty + 16 * a;   // mirror: col in iT range
#pragma unroll
                    for (int c = 0; c < 4; c++) {
                        int gi = jT * 32 + btx + 8 * c; // mirror: row in jT range
                        float et = fmaxf(-tv[a][c], 0.f);
                        size_t eo = ebase + (size_t)gi * Nn + gj;
                        float old = g_Eh[eo];
                        g_Eh[eo] = et;
                        float d = et - old;
                        g_Msum[mbase + (size_t)gi * Nn + gj] += d;
                        csum += d;
                    }
                    atomicAdd(&cbg[32 + bty + 16 * a], csum);
                }
            }
            __syncthreads();
            // merge colbufs to global
            if (tid < 256) {
                int g = tid >> 6, k = tid & 63;
                int uu = role * 4 + g;
                int jTT = c_jT[uu], iTT = c_iT[uu];
                if (k < 32) {
                    atomicAdd(&g_colsum[bA * Nn + jTT * 32 + k], cb[g * 64 + k]);
                } else if (iTT != jTT) {
                    atomicAdd(&g_colsum[bA * Nn + iTT * 32 + (k - 32)], cb[g * 64 + k]);
                }
            }
        }
        gsync_b(grp, lgen);

        // ================= phase C: s-reduction + GRU + next XW =================
        if (ac_on) {
            int n0 = nT * 32;
            float* hrS   = wk;          // [32][64]
            float* dinvS = wk + 2048;   // 256
            float* dxvS  = wk + 2304;   // 256
            float* part  = wk + 2560;   // 512
            float* sS    = wk + 3072;   // 32
            float* sIt   = wk + 3104;   // [32][12]
            float inv_cnt = 1.0f / cnt;

            if (tid < 256) {
                int i = tid;
                float cs = g_colsum[bA * Nn + i];
                float dv = 1.0f / sqrtf(cs * inv_cnt + 1.0f);
                dinvS[i] = dv;
                dxvS[i] = dv * x[(bA * Nn + i) * Tn + t];
            }
            if (t < Tn - 1) {
                for (int i = tid; i < 384; i += NT) {
                    int rr = i / 12, c = i - rr * 12;
                    int tt = t + 1 + c - (Wn - 1);
                    sIt[i] = (tt >= 0) ? x[(bA * Nn + n0 + rr) * Tn + tt] : 0.f;
                }
            }
            __syncthreads();
            {
                int c = tid & 31, g = tid >> 5;   // 16 groups of 16 i's
                float acc = 0.f;
                int ibase = g * 16;
#pragma unroll 8
                for (int k = 0; k < 16; k++) {
                    int i = ibase + k;
                    acc += g_Msum[((size_t)bA * Nn + i) * Nn + n0 + c] * dxvS[i];
                }
                part[g * 32 + c] = acc;
            }
            __syncthreads();
            if (tid < 32) {
                float sraw = 0.f;
#pragma unroll
                for (int g = 0; g < 16; g++) sraw += part[g * 32 + tid];
                int n = n0 + tid;
                float dj = dinvS[n];
                sS[tid] = dj * (sraw * inv_cnt + dj * x[(bA * Nn + n) * Tn + t]);
            }
            __syncthreads();

            float2 zz[2];
            // ---- z gate ----
            {
                float c0 = sCoef[f0], c1 = sCoef[f0 + 1];
                float d0 = sCoef[64 + f0], d1 = sCoef[64 + f0 + 1];
                float bz0 = sBias[128 + f0], bz1 = sBias[128 + f0 + 1];
                ull acc[2];
#pragma unroll
                for (int jy = 0; jy < 2; jy++) {
                    float s = sS[r0 + jy];
                    acc[jy] = pack2(s * c0 + d0 + bz0, s * c1 + d1 + bz1);
                }
#pragma unroll 4
                for (int ff = 0; ff < 64; ff += 4) {
                    float4 Hq[2];
#pragma unroll
                    for (int jy = 0; jy < 2; jy++) Hq[jy] = *(const float4*)&hS[(r0 + jy) * 64 + ff];
                    const float* Hp = (const float*)Hq;
#pragma unroll
                    for (int s = 0; s < 4; s++) {
                        ull wv = *(const ull*)&sWz[(ff + s) * 64 + f0];
#pragma unroll
                        for (int jy = 0; jy < 2; jy++) fma2(acc[jy], splat2(Hp[jy * 4 + s]), wv);
                    }
                }
#pragma unroll
                for (int jy = 0; jy < 2; jy++) {
                    float2 a = unpack2(acc[jy]);
                    zz[jy] = make_float2(1.0f / (1.0f + expf(-a.x)), 1.0f / (1.0f + expf(-a.y)));
                }
            }
            // ---- r gate -> hrS ----
            {
                float c0 = sCoef[128 + f0], c1 = sCoef[128 + f0 + 1];
                float d0 = sCoef[192 + f0], d1 = sCoef[192 + f0 + 1];
                float br0 = sBias[192 + f0], br1 = sBias[192 + f0 + 1];
                ull acc[2];
#pragma unroll
                for (int jy = 0; jy < 2; jy++) {
                    float s = sS[r0 + jy];
                    acc[jy] = pack2(s * c0 + d0 + br0, s * c1 + d1 + br1);
                }
#pragma unroll 4
                for (int ff = 0; ff < 64; ff += 4) {
                    float4 Hq[2];
#pragma unroll
                    for (int jy = 0; jy < 2; jy++) Hq[jy] = *(const float4*)&hS[(r0 + jy) * 64 + ff];
                    const float* Hp = (const float*)Hq;
#pragma unroll
                    for (int s = 0; s < 4; s++) {
                        ull wv = *(const ull*)&sWr[(ff + s) * 64 + f0];
#pragma unroll
                        for (int jy = 0; jy < 2; jy++) fma2(acc[jy], splat2(Hp[jy * 4 + s]), wv);
                    }
                }
#pragma unroll
                for (int jy = 0; jy < 2; jy++) {
                    float2 a = unpack2(acc[jy]);
                    float rv0 = 1.0f / (1.0f + expf(-a.x));
                    float rv1 = 1.0f / (1.0f + expf(-a.y));
                    float2 hv = *(const float2*)&hS[(r0 + jy) * 64 + f0];
                    *(float2*)&hrS[(r0 + jy) * 64 + f0] = make_float2(hv.x * rv0, hv.y * rv1);
                }
            }
            __syncwarp();
            // ---- h candidate + combine (rows r0..r0+1 are warp-private) ----
            {
                float c0 = sCoef[256 + f0], c1 = sCoef[256 + f0 + 1];
                float d0 = sCoef[320 + f0], d1 = sCoef[320 + f0 + 1];
                float bh0 = sBias[256 + f0], bh1 = sBias[256 + f0 + 1];
                ull acc[2];
#pragma unroll
                for (int jy = 0; jy < 2; jy++) {
                    float s = sS[r0 + jy];
                    acc[jy] = pack2(s * c0 + d0 + bh0, s * c1 + d1 + bh1);
                }
#pragma unroll 4
                for (int ff = 0; ff < 64; ff += 4) {
                    float4 Hq[2];
#pragma unroll
                    for (int jy = 0; jy < 2; jy++) Hq[jy] = *(const float4*)&hrS[(r0 + jy) * 64 + ff];
                    const float* Hp = (const float*)Hq;
#pragma unroll
                    for (int s = 0; s < 4; s++) {
                        ull wv = *(const ull*)&sWh[(ff + s) * 64 + f0];
#pragma unroll
                        for (int jy = 0; jy < 2; jy++) fma2(acc[jy], splat2(Hp[jy * 4 + s]), wv);
                    }
                }
                __syncwarp();
#pragma unroll
                for (int jy = 0; jy < 2; jy++) {
                    float2 a = unpack2(acc[jy]);
                    float ht0 = tanhf(a.x);
                    float ht1 = tanhf(a.y);
                    float2 hv = *(const float2*)&hS[(r0 + jy) * 64 + f0];
                    float hn0 = zz[jy].x * hv.x + (1.0f - zz[jy].x) * ht0;
                    float hn1 = zz[jy].y * hv.y + (1.0f - zz[jy].y) * ht1;
                    *(float2*)&hS[(r0 + jy) * 64 + f0] = make_float2(hn0, hn1);
                    if (t == Tn - 1)
                        *(float2*)&g_h[(bA * Nn + n0 + r0 + jy) * Hn + f0] = make_float2(hn0, hn1);
                }
            }
            // ---- next-step XW ----
            if (t < Tn - 1) {
                __syncthreads();
                ull acc[2] = {0ull, 0ull};
#pragma unroll
                for (int c = 0; c < Wn; c++) {
                    ull wv = *(const ull*)&sWg[c * 64 + f0];
#pragma unroll
                    for (int jy = 0; jy < 2; jy++) fma2(acc[jy], splat2(sIt[(r0 + jy) * 12 + c]), wv);
                }
#pragma unroll 4
                for (int c = 0; c < Hn; c++) {
                    ull wv = *(const ull*)&sWg[(Wn + c) * 64 + f0];
#pragma unroll
                    for (int jy = 0; jy < 2; jy++) fma2(acc[jy], splat2(hS[(r0 + jy) * 64 + c]), wv);
                }
#pragma unroll
                for (int jy = 0; jy < 2; jy++)
                    *(float2*)&g_XW[(bA * Nn + n0 + r0 + jy) * EDn + f0] = unpack2(acc[jy]);
            }
        }
        gsync_b(grp, lgen);
    }
}

// ---------------- final classifier ----------------
__global__ __launch_bounds__(256) void k_cls(const float* __restrict__ cls_w,
                                             const float* __restrict__ cls_b,
                                             float* __restrict__ out) {
    int b = blockIdx.x, tid = threadIdx.x;
    float acc[4] = {0.f, 0.f, 0.f, 0.f};
    for (int i = tid; i < Nn * Hn; i += 256) {
        float hv = g_h[b * Nn * Hn + i];
#pragma unroll
        for (int c = 0; c < 4; c++) acc[c] += hv * cls_w[i * Cn + c];
    }
    __shared__ float red[4][256];
#pragma unroll
    for (int c = 0; c < 4; c++) red[c][tid] = acc[c];
    __syncthreads();
    for (int s = 128; s > 0; s >>= 1) {
        if (tid < s) {
#pragma unroll
            for (int c = 0; c < 4; c++) red[c][tid] += red[c][tid + s];
        }
        __syncthreads();
    }
    if (tid < 4) out[b * Cn + tid] = red[tid][0] + cls_b[tid];
}

// ---------------- launch ----------------
extern "C" void kernel_launch(void* const* d_in, const int* in_sizes, int n_in,
                              void* d_out, int out_size) {
    const float* x        = (const float*)d_in[0];
    const float* ew       = (const float*)d_in[1];
    const float* gconv_w  = (const float*)d_in[2];
    const float* gconv_b  = (const float*)d_in[3];
    const float* w1       = (const float*)d_in[4];
    const float* b1       = (const float*)d_in[5];
    const float* w2       = (const float*)d_in[6];
    const float* b2       = (const float*)d_in[7];
    const float* wz_c     = (const float*)d_in[8];
    const float* bz_c     = (const float*)d_in[9];
    const float* wz_l     = (const float*)d_in[10];
    const float* bz_l     = (const float*)d_in[11];
    const float* wr_c     = (const float*)d_in[12];
    const float* br_c     = (const float*)d_in[13];
    const float* wr_l     = (const float*)d_in[14];
    const float* br_l     = (const float*)d_in[15];
    const float* wh_c     = (const float*)d_in[16];
    const float* bh_c     = (const float*)d_in[17];
    const float* wh_l     = (const float*)d_in[18];
    const float* bh_l     = (const float*)d_in[19];
    const float* cls_w    = (const float*)d_in[20];
    const float* cls_b    = (const float*)d_in[21];
    const int*   eidx     = (const int*)d_in[22];
    float* out = (float*)d_out;

    static int smem_set = 0;
    if (!smem_set) {
        cudaFuncSetAttribute(k_persist, cudaFuncAttributeMaxDynamicSharedMemorySize, SMEM_BYTES);
        smem_set = 1;
    }

    k_zero<<<2048, 256>>>();
    k_build<<<1, 256>>>(eidx, ew);
    k_precoef<<<1, 64>>>(wz_c, wz_l, bz_c, wr_c, wr_l, br_c, wh_c, wh_l, bh_c);
    k_persist<<<NBLK, NT, SMEM_BYTES>>>(x, gconv_w, gconv_b, w1, b1, w2, b2,
                                        bz_l, wz_l, br_l, wr_l, bh_l, wh_l);
    k_cls<<<Bn, 256>>>(cls_w, cls_b, out);
}

// round 15
// speedup vs baseline: 3.0204x; 3.0204x over previous
#include <cuda_runtime.h>
#include <math.h>

#define Bn 16
#define Nn 256
#define Tn 64
#define Wn 12
#define Hn 64
#define EDn 64
#define Sn 5
#define Cn 4
#define En 2048
#define FGn 76   // W + H
#define CAP 64
#define GBLK 9            // blocks per batch group
#define NBLK (Bn * GBLK)  // 144
#define NT 512            // threads per block

typedef unsigned long long ull;

// ---------------- f32x2 packed-FMA helpers (sm_103a FFMA2) ----------------
__device__ __forceinline__ void fma2(ull& d, ull a, ull b) {
    asm("fma.rn.f32x2 %0, %1, %2, %0;" : "+l"(d) : "l"(a), "l"(b));
}
__device__ __forceinline__ ull splat2(float v) {
    ull r; asm("mov.b64 %0, {%1, %1};" : "=l"(r) : "f"(v)); return r;
}
__device__ __forceinline__ ull pack2(float lo, float hi) {
    ull r; asm("mov.b64 %0, {%1, %2};" : "=l"(r) : "f"(lo), "f"(hi)); return r;
}
__device__ __forceinline__ float2 unpack2(ull v) {
    float lo, hi; asm("mov.b64 {%0, %1}, %2;" : "=f"(lo), "=f"(hi) : "l"(v));
    return make_float2(lo, hi);
}
__device__ __forceinline__ float hadd2(ull v) { float2 f = unpack2(v); return f.x + f.y; }

// triangular pair LUT (36 pairs of 8x8 tiles)
__device__ __constant__ signed char c_iT[36] =
    {0,0,0,0,0,0,0,0, 1,1,1,1,1,1,1, 2,2,2,2,2,2, 3,3,3,3,3, 4,4,4,4, 5,5,5, 6,6, 7};
__device__ __constant__ signed char c_jT[36] =
    {0,1,2,3,4,5,6,7, 1,2,3,4,5,6,7, 2,3,4,5,6,7, 3,4,5,6,7, 4,5,6,7, 5,6,7, 6,7, 7};

// ---------------- device scratch ----------------
__device__ float g_dinv_stat[Nn];
__device__ int   g_nbr_cnt[Nn];
__device__ int   g_nbr_idx[Nn * CAP];
__device__ float g_nbr_w[Nn * CAP];
__device__ float g_coef[6 * Hn];
__device__ float g_XW[Bn * Nn * EDn];
__device__ float g_de1[Bn * Nn * EDn];
__device__ float g_de2[Bn * Nn * EDn];
__device__ float g_Eh[(size_t)Bn * Sn * Nn * Nn];
__device__ float g_Msum[(size_t)Bn * Nn * Nn];
__device__ float g_colsum[Bn * Nn];
__device__ float g_h[Bn * Nn * Hn];
__device__ unsigned g_bcount[Bn * 32];
__device__ unsigned g_bgen[Bn * 32];

// ---------------- smem layout (floats) ----------------
#define OFF_W1   0
#define OFF_W2   4096
#define OFF_WZ   8192
#define OFF_WR   12288
#define OFF_WH   16384
#define OFF_WG   20480          // 4864
#define OFF_COEF 25344          // 384
#define OFF_BIAS 25728          // 384: [b1,b2,bz,br,bh,gconv_b]
#define OFF_H    26112          // 2048 persistent h rows
#define OFF_NBRW 28160          // 2048
#define OFF_NBRI 30208          // 2048 (int view)
#define OFF_NBRC 32256          // 32 (int view)
#define OFF_WK   32288          // work area: 2 groups x GSZ
#define GSZ      10880          // d(8704) + tS(1024) + tS2(1024) + colbuf(128 = 2 passes x 64)
#define SMEM_FLOATS (OFF_WK + 2 * GSZ)
#define SMEM_BYTES (SMEM_FLOATS * 4)

// ---------------- per-batch grid barrier (9 arrivals) ----------------
__device__ __forceinline__ void gsync_b(int grp, unsigned& lgen) {
    __syncthreads();
    if (threadIdx.x == 0) {
        unsigned* cnt = &g_bcount[grp * 32];
        unsigned* gen = &g_bgen[grp * 32];
        __threadfence();
        if (atomicAdd(cnt, 1u) == (unsigned)(GBLK - 1)) {
            *cnt = 0u;
            __threadfence();
            atomicAdd(gen, 1u);
        } else {
            while (atomicAdd(gen, 0u) <= lgen) { __nanosleep(20); }
        }
        __threadfence();
    }
    lgen++;
    __syncthreads();
}

// ---------------- setup kernels ----------------
__global__ void k_zero() {
    size_t idx = (size_t)blockIdx.x * blockDim.x + threadIdx.x;
    size_t str = (size_t)gridDim.x * blockDim.x;
    if (idx < Bn * 32) { g_bcount[idx] = 0u; g_bgen[idx] = 0u; }
    for (size_t i = idx; i < (size_t)Bn * Sn * Nn * Nn; i += str) g_Eh[i] = 0.f;
    for (size_t i = idx; i < (size_t)Bn * Nn * Nn; i += str) g_Msum[i] = 0.f;
    for (size_t i = idx; i < (size_t)Bn * Nn; i += str) g_colsum[i] = 0.f;
}

__global__ void k_build(const int* __restrict__ ei, const float* __restrict__ ew) {
    int j = threadIdx.x;  // 256 threads, 1 block
    float deg = 1.0f;
    for (int e = 0; e < En; e++)
        if (ei[En + e] == j) deg += ew[e];
    g_dinv_stat[j] = 1.0f / sqrtf(deg);
    __syncthreads();
    float dj = g_dinv_stat[j];
    int cnt = 1;
    g_nbr_idx[j * CAP] = j;
    g_nbr_w[j * CAP] = dj * dj;
    for (int e = 0; e < En; e++) {
        if (ei[En + e] == j && cnt < CAP) {
            int s = ei[e];
            g_nbr_idx[j * CAP + cnt] = s;
            g_nbr_w[j * CAP + cnt] = g_dinv_stat[s] * ew[e] * dj;
            cnt++;
        }
    }
    g_nbr_cnt[j] = cnt;
}

__global__ void k_precoef(const float* wz_c, const float* wz_l, const float* bz_c,
                          const float* wr_c, const float* wr_l, const float* br_c,
                          const float* wh_c, const float* wh_l, const float* bh_c) {
    int k = threadIdx.x;  // 64 threads
    float az = 0, cz = 0, ar = 0, cr = 0, ah = 0, ch = 0;
    for (int f = 0; f < Hn; f++) {
        float wzl = wz_l[f * Hn + k], wrl = wr_l[f * Hn + k], whl = wh_l[f * Hn + k];
        az += wz_c[f] * wzl;  cz += bz_c[f] * wzl;
        ar += wr_c[f] * wrl;  cr += br_c[f] * wrl;
        ah += wh_c[f] * whl;  ch += bh_c[f] * whl;
    }
    g_coef[k] = az;        g_coef[64 + k] = cz;
    g_coef[128 + k] = ar;  g_coef[192 + k] = cr;
    g_coef[256 + k] = ah;  g_coef[320 + k] = ch;
}

// ---------------- persistent kernel: whole T-step scan ----------------
__global__ __launch_bounds__(NT, 1) void k_persist(
    const float* __restrict__ x, const float* __restrict__ Wg,
    const float* __restrict__ gconv_b,
    const float* __restrict__ w1, const float* __restrict__ b1,
    const float* __restrict__ w2, const float* __restrict__ b2,
    const float* __restrict__ bz_lf, const float* __restrict__ wz_l,
    const float* __restrict__ br_lf, const float* __restrict__ wr_l,
    const float* __restrict__ bh_lf, const float* __restrict__ wh_l)
{
    extern __shared__ float sm[];
    int tid = threadIdx.x, bid = blockIdx.x;
    int grp = bid / GBLK;          // batch
    int role = bid - grp * GBLK;   // 0..8
    int bA = grp, nT = role;
    bool ac_on = (role < 8);
    unsigned lgen = 0;

    float* sW1 = sm + OFF_W1;
    float* sW2 = sm + OFF_W2;
    float* sWz = sm + OFF_WZ;
    float* sWr = sm + OFF_WR;
    float* sWh = sm + OFF_WH;
    float* sWg = sm + OFF_WG;
    float* sCoef = sm + OFF_COEF;
    float* sBias = sm + OFF_BIAS;
    float* hS = sm + OFF_H;
    float* sNbrW = sm + OFF_NBRW;
    int* sNbrI = (int*)(sm + OFF_NBRI);
    int* sNbrC = (int*)(sm + OFF_NBRC);
    float* wk = sm + OFF_WK;

    // ---- load all weights once ----
    for (int i = tid; i < 4096; i += NT) {
        sW1[i] = w1[i];
        sW2[i] = w2[i];
        int r = i >> 6, c = i & 63;
        sWz[i] = wz_l[(64 + r) * 64 + c];
        sWr[i] = wr_l[(64 + r) * 64 + c];
        sWh[i] = wh_l[(64 + r) * 64 + c];
    }
    for (int i = tid; i < FGn * 64; i += NT) sWg[i] = Wg[i];
    for (int i = tid; i < 384; i += NT) sCoef[i] = g_coef[i];
    if (tid < 64) {
        sBias[tid] = b1[tid];        sBias[64 + tid] = b2[tid];
        sBias[128 + tid] = bz_lf[tid]; sBias[192 + tid] = br_lf[tid];
        sBias[256 + tid] = bh_lf[tid]; sBias[320 + tid] = gconv_b[tid];
    }
    for (int i = tid; i < 2048; i += NT) hS[i] = 0.f;

    if (ac_on) {
        for (int i = tid; i < 32 * CAP; i += NT) {
            sNbrI[i] = g_nbr_idx[nT * 32 * CAP + i];
            sNbrW[i] = g_nbr_w[nT * 32 * CAP + i];
        }
        if (tid < 32) sNbrC[tid] = g_nbr_cnt[nT * 32 + tid];
    }
    __syncthreads();

    int tx = tid & 31, ty = tid >> 5;   // ty 0..15
    int f0 = tx * 2, r0 = ty * 2;       // 2-row register tiles (phases A/C)

    // phase B decomposition: two 256-thread tile groups
    int tg = tid >> 8;                  // 0/1
    int ttid = tid & 255;
    int btx = ttid & 15, bty = ttid >> 4;   // 16x16 thread grid per group

    // ---- initial XW (t=0, h=0) ----
    if (ac_on) {
        float* sIt = wk;  // [32][12]
        for (int i = tid; i < 384; i += NT) {
            int rr = i / 12, c = i - rr * 12;
            int tt = c - (Wn - 1);
            sIt[i] = (tt >= 0) ? x[(bA * Nn + nT * 32 + rr) * Tn + tt] : 0.f;
        }
        __syncthreads();
        ull acc[2] = {0ull, 0ull};
#pragma unroll
        for (int c = 0; c < Wn; c++) {
            ull wv = *(const ull*)&sWg[c * 64 + f0];
#pragma unroll
            for (int jy = 0; jy < 2; jy++) fma2(acc[jy], splat2(sIt[(r0 + jy) * 12 + c]), wv);
        }
#pragma unroll
        for (int jy = 0; jy < 2; jy++)
            *(float2*)&g_XW[(bA * Nn + nT * 32 + r0 + jy) * EDn + f0] = unpack2(acc[jy]);
    }
    gsync_b(grp, lgen);

    for (int t = 0; t < Tn; t++) {
        int slot = t % Sn;
        float cnt = (float)((t + 1 < Sn) ? (t + 1) : Sn);

        // ================= phase A: df gather (interleaved MLP) + de1/de2 =================
        if (ac_on) {
            float* dfS = wk;  // [32][64]
            {
                int f = tid & 63, jg = tid >> 6;   // jg 0..7
                float gb = sBias[320 + f];
                float acc[4] = {0.f, 0.f, 0.f, 0.f};
                int nc[4];
                int mx = 0;
#pragma unroll
                for (int q = 0; q < 4; q++) {
                    nc[q] = sNbrC[jg + q * 8];
                    mx = (nc[q] > mx) ? nc[q] : mx;
                }
                for (int k = 0; k < mx; k++) {
#pragma unroll
                    for (int q = 0; q < 4; q++) {
                        if (k < nc[q]) {
                            int jl = jg + q * 8;
                            int i = sNbrI[jl * CAP + k];
                            float w = sNbrW[jl * CAP + k];
                            acc[q] += w * g_XW[(bA * Nn + i) * EDn + f];
                        }
                    }
                }
#pragma unroll
                for (int q = 0; q < 4; q++)
                    dfS[(jg + q * 8) * 64 + f] = acc[q] + gb;
            }
            __syncthreads();
            ull a1[2], a2[2];
#pragma unroll
            for (int jy = 0; jy < 2; jy++) { a1[jy] = 0ull; a2[jy] = 0ull; }
#pragma unroll 4
            for (int ff = 0; ff < 64; ff += 4) {
                float4 D[2];
#pragma unroll
                for (int jy = 0; jy < 2; jy++) D[jy] = *(const float4*)&dfS[(r0 + jy) * 64 + ff];
                const float* Dp = (const float*)D;
#pragma unroll
                for (int s = 0; s < 4; s++) {
                    ull w1v = *(const ull*)&sW1[(ff + s) * 64 + f0];
                    ull w2v = *(const ull*)&sW2[(ff + s) * 64 + f0];
#pragma unroll
                    for (int jy = 0; jy < 2; jy++) {
                        ull dv = splat2(Dp[jy * 4 + s]);
                        fma2(a1[jy], dv, w1v);
                        fma2(a2[jy], dv, w2v);
                    }
                }
            }
            {
                float bb10 = sBias[f0], bb11 = sBias[f0 + 1];
                float bb20 = sBias[64 + f0], bb21 = sBias[64 + f0 + 1];
#pragma unroll
                for (int jy = 0; jy < 2; jy++) {
                    int row = (bA * Nn + nT * 32 + r0 + jy) * EDn;
                    float2 v1 = unpack2(a1[jy]);
                    float2 v2 = unpack2(a2[jy]);
                    *(float2*)&g_de1[row + f0] = make_float2(tanhf(v1.x + bb10), tanhf(v1.y + bb11));
                    *(float2*)&g_de2[row + f0] = make_float2(tanhf(v2.x + bb20), tanhf(v2.y + bb21));
                }
            }
        }
        gsync_b(grp, lgen);

        // ========= phase B: Et tiles — 2 passes x 2 concurrent tile groups =========
        {
            float* gb_ = wk + tg * GSZ;
            float* d1i = gb_;
            float* d2i = gb_ + 2176;
            float* d1j = gb_ + 4352;
            float* d2j = gb_ + 6528;
            float* tS  = gb_ + 8704;    // [32][32]
            float* tS2 = gb_ + 9728;    // [32][32] mirror (relu(-t), transposed)
            float* colbuf = gb_ + 10752;   // 128: pass k2 uses [k2*64, k2*64+64)
            if (ttid < 128) colbuf[ttid] = 0.f;
#pragma unroll 1
            for (int k2 = 0; k2 < 2; k2++) {
                int u = role * 4 + k2 * 2 + tg;   // 36 = 9*4, always valid
                int iT = c_iT[u], jT = c_jT[u];
                bool diag = (iT == jT);
                float* cbp = colbuf + k2 * 64;

                for (int i = ttid; i < 512; i += 256) {
                    int rr = i >> 4, e = (i & 15) * 4;
                    int gi = (bA * Nn + iT * 32 + rr) * EDn + e;
                    int gj = (bA * Nn + jT * 32 + rr) * EDn + e;
                    *(float4*)&d1i[rr * 68 + e] = *(const float4*)&g_de1[gi];
                    *(float4*)&d2i[rr * 68 + e] = *(const float4*)&g_de2[gi];
                    *(float4*)&d1j[rr * 68 + e] = *(const float4*)&g_de1[gj];
                    *(float4*)&d2j[rr * 68 + e] = *(const float4*)&g_de2[gj];
                }
                __syncthreads();

                // 2x2 cells: rows bty,bty+16; cols btx,btx+16
                ull accA[2][2], accB[2][2];
#pragma unroll
                for (int a = 0; a < 2; a++)
#pragma unroll
                    for (int c = 0; c < 2; c++) { accA[a][c] = 0ull; accB[a][c] = 0ull; }
#pragma unroll
                for (int e0 = 0; e0 < 64; e0 += 4) {
                    ulonglong2 P1[2], P2[2], Q1[2], Q2[2];
#pragma unroll
                    for (int a = 0; a < 2; a++) {
                        P1[a] = *(const ulonglong2*)&d1i[(bty + 16 * a) * 68 + e0];
                        P2[a] = *(const ulonglong2*)&d2i[(bty + 16 * a) * 68 + e0];
                    }
#pragma unroll
                    for (int c = 0; c < 2; c++) {
                        Q1[c] = *(const ulonglong2*)&d1j[(btx + 16 * c) * 68 + e0];
                        Q2[c] = *(const ulonglong2*)&d2j[(btx + 16 * c) * 68 + e0];
                    }
#pragma unroll
                    for (int a = 0; a < 2; a++)
#pragma unroll
                        for (int c = 0; c < 2; c++) {
                            fma2(accA[a][c], P1[a].x, Q2[c].x);  fma2(accA[a][c], P1[a].y, Q2[c].y);
                            fma2(accB[a][c], Q1[c].x, P2[a].x);  fma2(accB[a][c], Q1[c].y, P2[a].y);
                        }
                }
#pragma unroll
                for (int a = 0; a < 2; a++)
#pragma unroll
                    for (int c = 0; c < 2; c++) {
                        float tv = tanhf(hadd2(accA[a][c]) - hadd2(accB[a][c]));
                        tS[(bty + 16 * a) * 32 + btx + 16 * c] = tv;
                        tS2[(btx + 16 * c) * 32 + bty + 16 * a] = fmaxf(-tv, 0.f);
                    }
                __syncthreads();

                // fused RMW: per-thread 4-row column strip (coalesced rows)
                size_t ebase = ((size_t)(bA * Sn + slot) * Nn) * Nn;
                size_t mbase = ((size_t)bA * Nn) * Nn;
                int cc = ttid & 31, rg = ttid >> 5;   // 8 groups x 4 rows
                {
                    float csum = 0.f;
#pragma unroll
                    for (int k = 0; k < 4; k++) {
                        int r = rg * 4 + k;
                        float et = fmaxf(tS[r * 32 + cc], 0.f);
                        size_t eo = ebase + (size_t)(iT * 32 + r) * Nn + jT * 32 + cc;
                        float old = g_Eh[eo];
                        g_Eh[eo] = et;
                        float d = et - old;
                        g_Msum[mbase + (size_t)(iT * 32 + r) * Nn + jT * 32 + cc] += d;
                        csum += d;
                    }
                    atomicAdd(&cbp[cc], csum);
                }
                if (!diag) {
                    float csum = 0.f;
#pragma unroll
                    for (int k = 0; k < 4; k++) {
                        int r = rg * 4 + k;
                        float et = tS2[r * 32 + cc];
                        size_t eo = ebase + (size_t)(jT * 32 + r) * Nn + iT * 32 + cc;
                        float old = g_Eh[eo];
                        g_Eh[eo] = et;
                        float d = et - old;
                        g_Msum[mbase + (size_t)(jT * 32 + r) * Nn + iT * 32 + cc] += d;
                        csum += d;
                    }
                    atomicAdd(&cbp[32 + cc], csum);
                }
                // no sync here: next pass's post-load sync orders tS restaging;
                // colbuf halves are disjoint across passes
            }
            __syncthreads();
            // merge both passes' colbufs to global
            if (ttid < 128) {
                int k2 = ttid >> 6, k = ttid & 63;
                int u = role * 4 + k2 * 2 + tg;
                int iTT = c_iT[u], jTT = c_jT[u];
                if (k < 32) {
                    atomicAdd(&g_colsum[bA * Nn + jTT * 32 + k], colbuf[k2 * 64 + k]);
                } else if (iTT != jTT) {
                    atomicAdd(&g_colsum[bA * Nn + iTT * 32 + (k - 32)], colbuf[k2 * 64 + k]);
                }
            }
        }
        gsync_b(grp, lgen);

        // ================= phase C: s-reduction + GRU + next XW =================
        if (ac_on) {
            int n0 = nT * 32;
            float* hrS   = wk;          // [32][64]
            float* dinvS = wk + 2048;   // 256
            float* dxvS  = wk + 2304;   // 256
            float* part  = wk + 2560;   // 512
            float* sS    = wk + 3072;   // 32
            float* sIt   = wk + 3104;   // [32][12]
            float inv_cnt = 1.0f / cnt;

            if (tid < 256) {
                int i = tid;
                float cs = g_colsum[bA * Nn + i];
                float dv = 1.0f / sqrtf(cs * inv_cnt + 1.0f);
                dinvS[i] = dv;
                dxvS[i] = dv * x[(bA * Nn + i) * Tn + t];
            }
            if (t < Tn - 1) {
                for (int i = tid; i < 384; i += NT) {
                    int rr = i / 12, c = i - rr * 12;
                    int tt = t + 1 + c - (Wn - 1);
                    sIt[i] = (tt >= 0) ? x[(bA * Nn + n0 + rr) * Tn + tt] : 0.f;
                }
            }
            __syncthreads();
            {
                int c = tid & 31, g = tid >> 5;   // 16 groups of 16 i's
                float acc = 0.f;
                int ibase = g * 16;
#pragma unroll 8
                for (int k = 0; k < 16; k++) {
                    int i = ibase + k;
                    acc += g_Msum[((size_t)bA * Nn + i) * Nn + n0 + c] * dxvS[i];
                }
                part[g * 32 + c] = acc;
            }
            __syncthreads();
            if (tid < 32) {
                float sraw = 0.f;
#pragma unroll
                for (int g = 0; g < 16; g++) sraw += part[g * 32 + tid];
                int n = n0 + tid;
                float dj = dinvS[n];
                sS[tid] = dj * (sraw * inv_cnt + dj * x[(bA * Nn + n) * Tn + t]);
            }
            __syncthreads();

            float2 zz[2];
            // ---- z gate ----
            {
                float c0 = sCoef[f0], c1 = sCoef[f0 + 1];
                float d0 = sCoef[64 + f0], d1 = sCoef[64 + f0 + 1];
                float bz0 = sBias[128 + f0], bz1 = sBias[128 + f0 + 1];
                ull acc[2];
#pragma unroll
                for (int jy = 0; jy < 2; jy++) {
                    float s = sS[r0 + jy];
                    acc[jy] = pack2(s * c0 + d0 + bz0, s * c1 + d1 + bz1);
                }
#pragma unroll 4
                for (int ff = 0; ff < 64; ff += 4) {
                    float4 Hq[2];
#pragma unroll
                    for (int jy = 0; jy < 2; jy++) Hq[jy] = *(const float4*)&hS[(r0 + jy) * 64 + ff];
                    const float* Hp = (const float*)Hq;
#pragma unroll
                    for (int s = 0; s < 4; s++) {
                        ull wv = *(const ull*)&sWz[(ff + s) * 64 + f0];
#pragma unroll
                        for (int jy = 0; jy < 2; jy++) fma2(acc[jy], splat2(Hp[jy * 4 + s]), wv);
                    }
                }
#pragma unroll
                for (int jy = 0; jy < 2; jy++) {
                    float2 a = unpack2(acc[jy]);
                    zz[jy] = make_float2(1.0f / (1.0f + expf(-a.x)), 1.0f / (1.0f + expf(-a.y)));
                }
            }
            // ---- r gate -> hrS ----
            {
                float c0 = sCoef[128 + f0], c1 = sCoef[128 + f0 + 1];
                float d0 = sCoef[192 + f0], d1 = sCoef[192 + f0 + 1];
                float br0 = sBias[192 + f0], br1 = sBias[192 + f0 + 1];
                ull acc[2];
#pragma unroll
                for (int jy = 0; jy < 2; jy++) {
                    float s = sS[r0 + jy];
                    acc[jy] = pack2(s * c0 + d0 + br0, s * c1 + d1 + br1);
                }
#pragma unroll 4
                for (int ff = 0; ff < 64; ff += 4) {
                    float4 Hq[2];
#pragma unroll
                    for (int jy = 0; jy < 2; jy++) Hq[jy] = *(const float4*)&hS[(r0 + jy) * 64 + ff];
                    const float* Hp = (const float*)Hq;
#pragma unroll
                    for (int s = 0; s < 4; s++) {
                        ull wv = *(const ull*)&sWr[(ff + s) * 64 + f0];
#pragma unroll
                        for (int jy = 0; jy < 2; jy++) fma2(acc[jy], splat2(Hp[jy * 4 + s]), wv);
                    }
                }
#pragma unroll
                for (int jy = 0; jy < 2; jy++) {
                    float2 a = unpack2(acc[jy]);
                    float rv0 = 1.0f / (1.0f + expf(-a.x));
                    float rv1 = 1.0f / (1.0f + expf(-a.y));
                    float2 hv = *(const float2*)&hS[(r0 + jy) * 64 + f0];
                    *(float2*)&hrS[(r0 + jy) * 64 + f0] = make_float2(hv.x * rv0, hv.y * rv1);
                }
            }
            __syncwarp();
            // ---- h candidate + combine (rows r0..r0+1 are warp-private) ----
            {
                float c0 = sCoef[256 + f0], c1 = sCoef[256 + f0 + 1];
                float d0 = sCoef[320 + f0], d1 = sCoef[320 + f0 + 1];
                float bh0 = sBias[256 + f0], bh1 = sBias[256 + f0 + 1];
                ull acc[2];
#pragma unroll
                for (int jy = 0; jy < 2; jy++) {
                    float s = sS[r0 + jy];
                    acc[jy] = pack2(s * c0 + d0 + bh0, s * c1 + d1 + bh1);
                }
#pragma unroll 4
                for (int ff = 0; ff < 64; ff += 4) {
                    float4 Hq[2];
#pragma unroll
                    for (int jy = 0; jy < 2; jy++) Hq[jy] = *(const float4*)&hrS[(r0 + jy) * 64 + ff];
                    const float* Hp = (const float*)Hq;
#pragma unroll
                    for (int s = 0; s < 4; s++) {
                        ull wv = *(const ull*)&sWh[(ff + s) * 64 + f0];
#pragma unroll
                        for (int jy = 0; jy < 2; jy++) fma2(acc[jy], splat2(Hp[jy * 4 + s]), wv);
                    }
                }
                __syncwarp();
#pragma unroll
                for (int jy = 0; jy < 2; jy++) {
                    float2 a = unpack2(acc[jy]);
                    float ht0 = tanhf(a.x);
                    float ht1 = tanhf(a.y);
                    float2 hv = *(const float2*)&hS[(r0 + jy) * 64 + f0];
                    float hn0 = zz[jy].x * hv.x + (1.0f - zz[jy].x) * ht0;
                    float hn1 = zz[jy].y * hv.y + (1.0f - zz[jy].y) * ht1;
                    *(float2*)&hS[(r0 + jy) * 64 + f0] = make_float2(hn0, hn1);
                    if (t == Tn - 1)
                        *(float2*)&g_h[(bA * Nn + n0 + r0 + jy) * Hn + f0] = make_float2(hn0, hn1);
                }
            }
            // ---- next-step XW ----
            if (t < Tn - 1) {
                __syncthreads();
                ull acc[2] = {0ull, 0ull};
#pragma unroll
                for (int c = 0; c < Wn; c++) {
                    ull wv = *(const ull*)&sWg[c * 64 + f0];
#pragma unroll
                    for (int jy = 0; jy < 2; jy++) fma2(acc[jy], splat2(sIt[(r0 + jy) * 12 + c]), wv);
                }
#pragma unroll 4
                for (int c = 0; c < Hn; c++) {
                    ull wv = *(const ull*)&sWg[(Wn + c) * 64 + f0];
#pragma unroll
                    for (int jy = 0; jy < 2; jy++) fma2(acc[jy], splat2(hS[(r0 + jy) * 64 + c]), wv);
                }
#pragma unroll
                for (int jy = 0; jy < 2; jy++)
                    *(float2*)&g_XW[(bA * Nn + n0 + r0 + jy) * EDn + f0] = unpack2(acc[jy]);
            }
        }
        gsync_b(grp, lgen);
    }
}

// ---------------- final classifier ----------------
__global__ __launch_bounds__(256) void k_cls(const float* __restrict__ cls_w,
                                             const float* __restrict__ cls_b,
                                             float* __restrict__ out) {
    int b = blockIdx.x, tid = threadIdx.x;
    float acc[4] = {0.f, 0.f, 0.f, 0.f};
    for (int i = tid; i < Nn * Hn; i += 256) {
        float hv = g_h[b * Nn * Hn + i];
#pragma unroll
        for (int c = 0; c < 4; c++) acc[c] += hv * cls_w[i * Cn + c];
    }
    __shared__ float red[4][256];
#pragma unroll
    for (int c = 0; c < 4; c++) red[c][tid] = acc[c];
    __syncthreads();
    for (int s = 128; s > 0; s >>= 1) {
        if (tid < s) {
#pragma unroll
            for (int c = 0; c < 4; c++) red[c][tid] += red[c][tid + s];
        }
        __syncthreads();
    }
    if (tid < 4) out[b * Cn + tid] = red[tid][0] + cls_b[tid];
}

// ---------------- launch ----------------
extern "C" void kernel_launch(void* const* d_in, const int* in_sizes, int n_in,
                              void* d_out, int out_size) {
    const float* x        = (const float*)d_in[0];
    const float* ew       = (const float*)d_in[1];
    const float* gconv_w  = (const float*)d_in[2];
    const float* gconv_b  = (const float*)d_in[3];
    const float* w1       = (const float*)d_in[4];
    const float* b1       = (const float*)d_in[5];
    const float* w2       = (const float*)d_in[6];
    const float* b2       = (const float*)d_in[7];
    const float* wz_c     = (const float*)d_in[8];
    const float* bz_c     = (const float*)d_in[9];
    const float* wz_l     = (const float*)d_in[10];
    const float* bz_l     = (const float*)d_in[11];
    const float* wr_c     = (const float*)d_in[12];
    const float* br_c     = (const float*)d_in[13];
    const float* wr_l     = (const float*)d_in[14];
    const float* br_l     = (const float*)d_in[15];
    const float* wh_c     = (const float*)d_in[16];
    const float* bh_c     = (const float*)d_in[17];
    const float* wh_l     = (const float*)d_in[18];
    const float* bh_l     = (const float*)d_in[19];
    const float* cls_w    = (const float*)d_in[20];
    const float* cls_b    = (const float*)d_in[21];
    const int*   eidx     = (const int*)d_in[22];
    float* out = (float*)d_out;

    static int smem_set = 0;
    if (!smem_set) {
        cudaFuncSetAttribute(k_persist, cudaFuncAttributeMaxDynamicSharedMemorySize, SMEM_BYTES);
        smem_set = 1;
    }

    k_zero<<<2048, 256>>>();
    k_build<<<1, 256>>>(eidx, ew);
    k_precoef<<<1, 64>>>(wz_c, wz_l, bz_c, wr_c, wr_l, br_c, wh_c, wh_l, bh_c);
    k_persist<<<NBLK, NT, SMEM_BYTES>>>(x, gconv_w, gconv_b, w1, b1, w2, b2,
                                        bz_l, wz_l, br_l, wr_l, bh_l, wh_l);
    k_cls<<<Bn, 256>>>(cls_w, cls_b, out);
}

// round 16
// speedup vs baseline: 3.3881x; 1.1217x over previous
#include <cuda_runtime.h>
#include <math.h>

#define Bn 16
#define Nn 256
#define Tn 64
#define Wn 12
#define Hn 64
#define EDn 64
#define Sn 5
#define Cn 4
#define En 2048
#define FGn 76   // W + H
#define CAP 64
#define GBLK 9            // blocks per batch group
#define NBLK (Bn * GBLK)  // 144
#define NT 512            // threads per block

typedef unsigned long long ull;

// ---------------- f32x2 packed-FMA helpers (sm_103a FFMA2) ----------------
__device__ __forceinline__ void fma2(ull& d, ull a, ull b) {
    asm("fma.rn.f32x2 %0, %1, %2, %0;" : "+l"(d) : "l"(a), "l"(b));
}
__device__ __forceinline__ ull splat2(float v) {
    ull r; asm("mov.b64 %0, {%1, %1};" : "=l"(r) : "f"(v)); return r;
}
__device__ __forceinline__ ull pack2(float lo, float hi) {
    ull r; asm("mov.b64 %0, {%1, %2};" : "=l"(r) : "f"(lo), "f"(hi)); return r;
}
__device__ __forceinline__ float2 unpack2(ull v) {
    float lo, hi; asm("mov.b64 {%0, %1}, %2;" : "=f"(lo), "=f"(hi) : "l"(v));
    return make_float2(lo, hi);
}
__device__ __forceinline__ float hadd2(ull v) { float2 f = unpack2(v); return f.x + f.y; }

// phase-B pair partition: role -> 4 pairs, each role spans <=4 distinct tiles
__device__ __constant__ signed char c_bi[9][4] = {
    {0,0,0,0}, {1,1,1,2}, {2,3,6,7}, {4,4,4,4}, {5,5,5,6},
    {0,0,1,1}, {0,0,1,1}, {2,2,3,3}, {2,2,3,3}};
__device__ __constant__ signed char c_bj[9][4] = {
    {0,1,2,3}, {1,2,3,3}, {2,3,6,7}, {4,5,6,7}, {5,6,7,7},
    {4,5,4,5}, {6,7,6,7}, {4,5,4,5}, {6,7,6,7}};
__device__ __constant__ signed char c_nload[9] = {4,3,4,4,3,4,4,4,4};
__device__ __constant__ signed char c_tiles[9][4] = {
    {0,1,2,3}, {1,2,3,3}, {2,3,6,7}, {4,5,6,7}, {5,6,7,7},
    {0,1,4,5}, {0,1,6,7}, {2,3,4,5}, {2,3,6,7}};
__device__ __constant__ signed char c_pi[9][4] = {
    {0,0,0,0}, {0,0,0,1}, {0,1,2,3}, {0,0,0,0}, {0,0,0,1},
    {0,0,1,1}, {0,0,1,1}, {0,0,1,1}, {0,0,1,1}};
__device__ __constant__ signed char c_pj[9][4] = {
    {0,1,2,3}, {0,1,2,2}, {0,1,2,3}, {0,1,2,3}, {0,1,2,2},
    {2,3,2,3}, {2,3,2,3}, {2,3,2,3}, {2,3,2,3}};

// ---------------- device scratch ----------------
__device__ float g_dinv_stat[Nn];
__device__ int   g_nbr_cnt[Nn];
__device__ int   g_nbr_idx[Nn * CAP];
__device__ float g_nbr_w[Nn * CAP];
__device__ float g_coef[6 * Hn];
__device__ float g_XW[Bn * Nn * EDn];
__device__ float g_de1[Bn * Nn * EDn];
__device__ float g_de2[Bn * Nn * EDn];
__device__ float g_Eh[(size_t)Bn * Sn * Nn * Nn];
__device__ float g_Msum[(size_t)Bn * Nn * Nn];
__device__ float g_colsum[Bn * Nn];
__device__ float g_h[Bn * Nn * Hn];
__device__ unsigned g_bcount[Bn * 32];
__device__ unsigned g_bgen[Bn * 32];

// ---------------- smem layout (floats) ----------------
#define OFF_W1   0
#define OFF_W2   4096
#define OFF_WZ   8192
#define OFF_WR   12288
#define OFF_WH   16384
#define OFF_WG   20480          // 4864
#define OFF_COEF 25344          // 384
#define OFF_BIAS 25728          // 384: [b1,b2,bz,br,bh,gconv_b]
#define OFF_H    26112          // 2048 persistent h rows
#define OFF_NBRW 28160          // 2048
#define OFF_NBRI 30208          // 2048 (int view)
#define OFF_NBRC 32256          // 32 (int view)
#define OFF_WK   32288
// phase B: 4 pool slots x (de1,de2) x 32x68 + 4 x tS(32x33) + colbuf(256)
#define DSLOT    4352           // 2 * 2176
#define OFF_TS   (4 * DSLOT)            // 17408 (relative to wk)
#define OFF_CBR  (OFF_TS + 4 * 1056)    // 21632 (relative to wk)
#define WKSZ     (OFF_CBR + 256)        // 21888
#define SMEM_FLOATS (OFF_WK + WKSZ)
#define SMEM_BYTES (SMEM_FLOATS * 4)

// ---------------- per-batch grid barrier (9 arrivals) ----------------
__device__ __forceinline__ void gsync_b(int grp, unsigned& lgen) {
    __syncthreads();
    if (threadIdx.x == 0) {
        unsigned* cnt = &g_bcount[grp * 32];
        unsigned* gen = &g_bgen[grp * 32];
        __threadfence();
        if (atomicAdd(cnt, 1u) == (unsigned)(GBLK - 1)) {
            *cnt = 0u;
            __threadfence();
            atomicAdd(gen, 1u);
        } else {
            while (atomicAdd(gen, 0u) <= lgen) { __nanosleep(20); }
        }
        __threadfence();
    }
    lgen++;
    __syncthreads();
}

// ---------------- setup kernels ----------------
__global__ void k_zero() {
    size_t idx = (size_t)blockIdx.x * blockDim.x + threadIdx.x;
    size_t str = (size_t)gridDim.x * blockDim.x;
    if (idx < Bn * 32) { g_bcount[idx] = 0u; g_bgen[idx] = 0u; }
    for (size_t i = idx; i < (size_t)Bn * Sn * Nn * Nn; i += str) g_Eh[i] = 0.f;
    for (size_t i = idx; i < (size_t)Bn * Nn * Nn; i += str) g_Msum[i] = 0.f;
    for (size_t i = idx; i < (size_t)Bn * Nn; i += str) g_colsum[i] = 0.f;
}

__global__ void k_build(const int* __restrict__ ei, const float* __restrict__ ew) {
    int j = threadIdx.x;  // 256 threads, 1 block
    float deg = 1.0f;
    for (int e = 0; e < En; e++)
        if (ei[En + e] == j) deg += ew[e];
    g_dinv_stat[j] = 1.0f / sqrtf(deg);
    __syncthreads();
    float dj = g_dinv_stat[j];
    int cnt = 1;
    g_nbr_idx[j * CAP] = j;
    g_nbr_w[j * CAP] = dj * dj;
    for (int e = 0; e < En; e++) {
        if (ei[En + e] == j && cnt < CAP) {
            int s = ei[e];
            g_nbr_idx[j * CAP + cnt] = s;
            g_nbr_w[j * CAP + cnt] = g_dinv_stat[s] * ew[e] * dj;
            cnt++;
        }
    }
    g_nbr_cnt[j] = cnt;
}

__global__ void k_precoef(const float* wz_c, const float* wz_l, const float* bz_c,
                          const float* wr_c, const float* wr_l, const float* br_c,
                          const float* wh_c, const float* wh_l, const float* bh_c) {
    int k = threadIdx.x;  // 64 threads
    float az = 0, cz = 0, ar = 0, cr = 0, ah = 0, ch = 0;
    for (int f = 0; f < Hn; f++) {
        float wzl = wz_l[f * Hn + k], wrl = wr_l[f * Hn + k], whl = wh_l[f * Hn + k];
        az += wz_c[f] * wzl;  cz += bz_c[f] * wzl;
        ar += wr_c[f] * wrl;  cr += br_c[f] * wrl;
        ah += wh_c[f] * whl;  ch += bh_c[f] * whl;
    }
    g_coef[k] = az;        g_coef[64 + k] = cz;
    g_coef[128 + k] = ar;  g_coef[192 + k] = cr;
    g_coef[256 + k] = ah;  g_coef[320 + k] = ch;
}

// ---------------- persistent kernel: whole T-step scan ----------------
__global__ __launch_bounds__(NT, 1) void k_persist(
    const float* __restrict__ x, const float* __restrict__ Wg,
    const float* __restrict__ gconv_b,
    const float* __restrict__ w1, const float* __restrict__ b1,
    const float* __restrict__ w2, const float* __restrict__ b2,
    const float* __restrict__ bz_lf, const float* __restrict__ wz_l,
    const float* __restrict__ br_lf, const float* __restrict__ wr_l,
    const float* __restrict__ bh_lf, const float* __restrict__ wh_l)
{
    extern __shared__ float sm[];
    int tid = threadIdx.x, bid = blockIdx.x;
    int grp = bid / GBLK;          // batch
    int role = bid - grp * GBLK;   // 0..8
    int bA = grp, nT = role;
    bool ac_on = (role < 8);
    unsigned lgen = 0;

    float* sW1 = sm + OFF_W1;
    float* sW2 = sm + OFF_W2;
    float* sWz = sm + OFF_WZ;
    float* sWr = sm + OFF_WR;
    float* sWh = sm + OFF_WH;
    float* sWg = sm + OFF_WG;
    float* sCoef = sm + OFF_COEF;
    float* sBias = sm + OFF_BIAS;
    float* hS = sm + OFF_H;
    float* sNbrW = sm + OFF_NBRW;
    int* sNbrI = (int*)(sm + OFF_NBRI);
    int* sNbrC = (int*)(sm + OFF_NBRC);
    float* wk = sm + OFF_WK;

    // ---- load all weights once ----
    for (int i = tid; i < 4096; i += NT) {
        sW1[i] = w1[i];
        sW2[i] = w2[i];
        int r = i >> 6, c = i & 63;
        sWz[i] = wz_l[(64 + r) * 64 + c];
        sWr[i] = wr_l[(64 + r) * 64 + c];
        sWh[i] = wh_l[(64 + r) * 64 + c];
    }
    for (int i = tid; i < FGn * 64; i += NT) sWg[i] = Wg[i];
    for (int i = tid; i < 384; i += NT) sCoef[i] = g_coef[i];
    if (tid < 64) {
        sBias[tid] = b1[tid];        sBias[64 + tid] = b2[tid];
        sBias[128 + tid] = bz_lf[tid]; sBias[192 + tid] = br_lf[tid];
        sBias[256 + tid] = bh_lf[tid]; sBias[320 + tid] = gconv_b[tid];
    }
    for (int i = tid; i < 2048; i += NT) hS[i] = 0.f;

    if (ac_on) {
        for (int i = tid; i < 32 * CAP; i += NT) {
            sNbrI[i] = g_nbr_idx[nT * 32 * CAP + i];
            sNbrW[i] = g_nbr_w[nT * 32 * CAP + i];
        }
        if (tid < 32) sNbrC[tid] = g_nbr_cnt[nT * 32 + tid];
    }
    __syncthreads();

    int tx = tid & 31, ty = tid >> 5;   // ty 0..15
    int f0 = tx * 2, r0 = ty * 2;       // 2-row register tiles (phases A/C)

    // phase B decomposition: 4 groups of 128 threads, one tile pair each
    int pg = tid >> 7;                  // 0..3
    int gt = tid & 127;
    int btx = gt & 15, bty = gt >> 4;   // 16 x 8 grid: cols {btx,btx+16}, rows {bty+8a}

    // ---- initial XW (t=0, h=0) ----
    if (ac_on) {
        float* sIt = wk;  // [32][12]
        for (int i = tid; i < 384; i += NT) {
            int rr = i / 12, c = i - rr * 12;
            int tt = c - (Wn - 1);
            sIt[i] = (tt >= 0) ? x[(bA * Nn + nT * 32 + rr) * Tn + tt] : 0.f;
        }
        __syncthreads();
        ull acc[2] = {0ull, 0ull};
#pragma unroll
        for (int c = 0; c < Wn; c++) {
            ull wv = *(const ull*)&sWg[c * 64 + f0];
#pragma unroll
            for (int jy = 0; jy < 2; jy++) fma2(acc[jy], splat2(sIt[(r0 + jy) * 12 + c]), wv);
        }
#pragma unroll
        for (int jy = 0; jy < 2; jy++)
            *(float2*)&g_XW[(bA * Nn + nT * 32 + r0 + jy) * EDn + f0] = unpack2(acc[jy]);
    }
    gsync_b(grp, lgen);

    for (int t = 0; t < Tn; t++) {
        int slot = t % Sn;
        float cnt = (float)((t + 1 < Sn) ? (t + 1) : Sn);

        // ================= phase A: df gather + de1/de2 =================
        if (ac_on) {
            float* dfS = wk;  // [32][64]
            {
                int f = tid & 63, jg = tid >> 6;   // jg 0..7
                float gb = sBias[320 + f];
#pragma unroll
                for (int q = 0; q < 4; q++) {
                    int jl = jg + q * 8;
                    int nc = sNbrC[jl];
                    float acc = 0.f;
                    for (int k = 0; k < nc; k++)
                        acc += sNbrW[jl * CAP + k] * g_XW[(bA * Nn + sNbrI[jl * CAP + k]) * EDn + f];
                    dfS[jl * 64 + f] = acc + gb;
                }
            }
            __syncthreads();
            ull a1[2], a2[2];
#pragma unroll
            for (int jy = 0; jy < 2; jy++) { a1[jy] = 0ull; a2[jy] = 0ull; }
#pragma unroll 4
            for (int ff = 0; ff < 64; ff += 4) {
                float4 D[2];
#pragma unroll
                for (int jy = 0; jy < 2; jy++) D[jy] = *(const float4*)&dfS[(r0 + jy) * 64 + ff];
                const float* Dp = (const float*)D;
#pragma unroll
                for (int s = 0; s < 4; s++) {
                    ull w1v = *(const ull*)&sW1[(ff + s) * 64 + f0];
                    ull w2v = *(const ull*)&sW2[(ff + s) * 64 + f0];
#pragma unroll
                    for (int jy = 0; jy < 2; jy++) {
                        ull dv = splat2(Dp[jy * 4 + s]);
                        fma2(a1[jy], dv, w1v);
                        fma2(a2[jy], dv, w2v);
                    }
                }
            }
            {
                float bb10 = sBias[f0], bb11 = sBias[f0 + 1];
                float bb20 = sBias[64 + f0], bb21 = sBias[64 + f0 + 1];
#pragma unroll
                for (int jy = 0; jy < 2; jy++) {
                    int row = (bA * Nn + nT * 32 + r0 + jy) * EDn;
                    float2 v1 = unpack2(a1[jy]);
                    float2 v2 = unpack2(a2[jy]);
                    *(float2*)&g_de1[row + f0] = make_float2(tanhf(v1.x + bb10), tanhf(v1.y + bb11));
                    *(float2*)&g_de2[row + f0] = make_float2(tanhf(v2.x + bb20), tanhf(v2.y + bb21));
                }
            }
        }
        gsync_b(grp, lgen);

        // ===== phase B: single pass — 4 concurrent pairs over a 4-slot tile pool =====
        {
            float* cb = wk + OFF_CBR;
            if (tid < 256) cb[tid] = 0.f;
            int nload = c_nload[role];
            for (int u = tid; u < nload * 1024; u += NT) {
                int slot_ = u >> 10;
                int rem = u & 1023;
                int mat = rem >> 9;
                int w = rem & 511;
                int rr = w >> 4, e4 = (w & 15) << 2;
                int tile = c_tiles[role][slot_];
                const float* src = mat ? g_de2 : g_de1;
                *(float4*)&wk[slot_ * DSLOT + mat * 2176 + rr * 68 + e4] =
                    *(const float4*)&src[(bA * Nn + tile * 32 + rr) * EDn + e4];
            }
            __syncthreads();

            int iT = c_bi[role][pg], jT = c_bj[role][pg];
            bool diag = (iT == jT);
            const float* d1i = wk + c_pi[role][pg] * DSLOT;
            const float* d2i = d1i + 2176;
            const float* d1j = wk + c_pj[role][pg] * DSLOT;
            const float* d2j = d1j + 2176;
            float* tS = wk + OFF_TS + pg * 1056;   // [32][33]

            // 4x2 cells: rows {bty+8a}, cols {btx+16c}
            ull accA[4][2], accB[4][2];
#pragma unroll
            for (int a = 0; a < 4; a++)
#pragma unroll
                for (int c = 0; c < 2; c++) { accA[a][c] = 0ull; accB[a][c] = 0ull; }
#pragma unroll
            for (int e0 = 0; e0 < 64; e0 += 4) {
                ulonglong2 P1[4], P2[4];
#pragma unroll
                for (int a = 0; a < 4; a++) {
                    P1[a] = *(const ulonglong2*)&d1i[(bty + 8 * a) * 68 + e0];
                    P2[a] = *(const ulonglong2*)&d2i[(bty + 8 * a) * 68 + e0];
                }
#pragma unroll
                for (int c = 0; c < 2; c++) {
                    ulonglong2 Q1 = *(const ulonglong2*)&d1j[(btx + 16 * c) * 68 + e0];
                    ulonglong2 Q2 = *(const ulonglong2*)&d2j[(btx + 16 * c) * 68 + e0];
#pragma unroll
                    for (int a = 0; a < 4; a++) {
                        fma2(accA[a][c], P1[a].x, Q2.x);  fma2(accA[a][c], P1[a].y, Q2.y);
                        fma2(accB[a][c], Q1.x, P2[a].x);  fma2(accB[a][c], Q1.y, P2[a].y);
                    }
                }
            }
#pragma unroll
            for (int a = 0; a < 4; a++)
#pragma unroll
                for (int c = 0; c < 2; c++)
                    tS[(bty + 8 * a) * 33 + btx + 16 * c] =
                        tanhf(hadd2(accA[a][c]) - hadd2(accB[a][c]));
            __syncthreads();

            // fused coalesced RMW: per-thread 8-row column strip
            size_t ebase = ((size_t)(bA * Sn + slot) * Nn) * Nn;
            size_t mbase = ((size_t)bA * Nn) * Nn;
            int cc = gt & 31, rg = gt >> 5;   // 4 row-groups x 8 rows
            float* cbg = cb + pg * 64;
            {
                float csum = 0.f;
#pragma unroll
                for (int k = 0; k < 8; k++) {
                    int r = rg * 8 + k;
                    float et = fmaxf(tS[r * 33 + cc], 0.f);
                    size_t eo = ebase + (size_t)(iT * 32 + r) * Nn + jT * 32 + cc;
                    float old = g_Eh[eo];
                    g_Eh[eo] = et;
                    float d = et - old;
                    g_Msum[mbase + (size_t)(iT * 32 + r) * Nn + jT * 32 + cc] += d;
                    csum += d;
                }
                atomicAdd(&cbg[cc], csum);
            }
            if (!diag) {
                float csum = 0.f;
#pragma unroll
                for (int k = 0; k < 8; k++) {
                    int r = rg * 8 + k;                      // mirror row (jT range)
                    float et = fmaxf(-tS[cc * 33 + r], 0.f); // transposed read, conflict-free
                    size_t eo = ebase + (size_t)(jT * 32 + r) * Nn + iT * 32 + cc;
                    float old = g_Eh[eo];
                    g_Eh[eo] = et;
                    float d = et - old;
                    g_Msum[mbase + (size_t)(jT * 32 + r) * Nn + iT * 32 + cc] += d;
                    csum += d;
                }
                atomicAdd(&cbg[32 + cc], csum);
            }
            __syncthreads();
            // merge colbufs to global
            if (tid < 256) {
                int g = tid >> 6, k = tid & 63;
                int iTT = c_bi[role][g], jTT = c_bj[role][g];
                if (k < 32) {
                    atomicAdd(&g_colsum[bA * Nn + jTT * 32 + k], cb[g * 64 + k]);
                } else if (iTT != jTT) {
                    atomicAdd(&g_colsum[bA * Nn + iTT * 32 + (k - 32)], cb[g * 64 + k]);
                }
            }
        }
        gsync_b(grp, lgen);

        // ================= phase C: s-reduction + GRU + next XW =================
        if (ac_on) {
            int n0 = nT * 32;
            float* hrS   = wk;          // [32][64]
            float* dinvS = wk + 2048;   // 256
            float* dxvS  = wk + 2304;   // 256
            float* part  = wk + 2560;   // 512
            float* sS    = wk + 3072;   // 32
            float* sIt   = wk + 3104;   // [32][12]
            float inv_cnt = 1.0f / cnt;

            if (tid < 256) {
                int i = tid;
                float cs = g_colsum[bA * Nn + i];
                float dv = 1.0f / sqrtf(cs * inv_cnt + 1.0f);
                dinvS[i] = dv;
                dxvS[i] = dv * x[(bA * Nn + i) * Tn + t];
            }
            if (t < Tn - 1) {
                for (int i = tid; i < 384; i += NT) {
                    int rr = i / 12, c = i - rr * 12;
                    int tt = t + 1 + c - (Wn - 1);
                    sIt[i] = (tt >= 0) ? x[(bA * Nn + n0 + rr) * Tn + tt] : 0.f;
                }
            }
            __syncthreads();
            {
                int c = tid & 31, g = tid >> 5;   // 16 groups of 16 i's
                float acc = 0.f;
                int ibase = g * 16;
#pragma unroll 8
                for (int k = 0; k < 16; k++) {
                    int i = ibase + k;
                    acc += g_Msum[((size_t)bA * Nn + i) * Nn + n0 + c] * dxvS[i];
                }
                part[g * 32 + c] = acc;
            }
            __syncthreads();
            if (tid < 32) {
                float sraw = 0.f;
#pragma unroll
                for (int g = 0; g < 16; g++) sraw += part[g * 32 + tid];
                int n = n0 + tid;
                float dj = dinvS[n];
                sS[tid] = dj * (sraw * inv_cnt + dj * x[(bA * Nn + n) * Tn + t]);
            }
            __syncthreads();

            float2 zz[2];
            // ---- z gate ----
            {
                float c0 = sCoef[f0], c1 = sCoef[f0 + 1];
                float d0 = sCoef[64 + f0], d1 = sCoef[64 + f0 + 1];
                float bz0 = sBias[128 + f0], bz1 = sBias[128 + f0 + 1];
                ull acc[2];
#pragma unroll
                for (int jy = 0; jy < 2; jy++) {
                    float s = sS[r0 + jy];
                    acc[jy] = pack2(s * c0 + d0 + bz0, s * c1 + d1 + bz1);
                }
#pragma unroll 4
                for (int ff = 0; ff < 64; ff += 4) {
                    float4 Hq[2];
#pragma unroll
                    for (int jy = 0; jy < 2; jy++) Hq[jy] = *(const float4*)&hS[(r0 + jy) * 64 + ff];
                    const float* Hp = (const float*)Hq;
#pragma unroll
                    for (int s = 0; s < 4; s++) {
                        ull wv = *(const ull*)&sWz[(ff + s) * 64 + f0];
#pragma unroll
                        for (int jy = 0; jy < 2; jy++) fma2(acc[jy], splat2(Hp[jy * 4 + s]), wv);
                    }
                }
#pragma unroll
                for (int jy = 0; jy < 2; jy++) {
                    float2 a = unpack2(acc[jy]);
                    zz[jy] = make_float2(1.0f / (1.0f + expf(-a.x)), 1.0f / (1.0f + expf(-a.y)));
                }
            }
            // ---- r gate -> hrS ----
            {
                float c0 = sCoef[128 + f0], c1 = sCoef[128 + f0 + 1];
                float d0 = sCoef[192 + f0], d1 = sCoef[192 + f0 + 1];
                float br0 = sBias[192 + f0], br1 = sBias[192 + f0 + 1];
                ull acc[2];
#pragma unroll
                for (int jy = 0; jy < 2; jy++) {
                    float s = sS[r0 + jy];
                    acc[jy] = pack2(s * c0 + d0 + br0, s * c1 + d1 + br1);
                }
#pragma unroll 4
                for (int ff = 0; ff < 64; ff += 4) {
                    float4 Hq[2];
#pragma unroll
                    for (int jy = 0; jy < 2; jy++) Hq[jy] = *(const float4*)&hS[(r0 + jy) * 64 + ff];
                    const float* Hp = (const float*)Hq;
#pragma unroll
                    for (int s = 0; s < 4; s++) {
                        ull wv = *(const ull*)&sWr[(ff + s) * 64 + f0];
#pragma unroll
                        for (int jy = 0; jy < 2; jy++) fma2(acc[jy], splat2(Hp[jy * 4 + s]), wv);
                    }
                }
#pragma unroll
                for (int jy = 0; jy < 2; jy++) {
                    float2 a = unpack2(acc[jy]);
                    float rv0 = 1.0f / (1.0f + expf(-a.x));
                    float rv1 = 1.0f / (1.0f + expf(-a.y));
                    float2 hv = *(const float2*)&hS[(r0 + jy) * 64 + f0];
                    *(float2*)&hrS[(r0 + jy) * 64 + f0] = make_float2(hv.x * rv0, hv.y * rv1);
                }
            }
            __syncwarp();
            // ---- h candidate + combine (rows r0..r0+1 are warp-private) ----
            {
                float c0 = sCoef[256 + f0], c1 = sCoef[256 + f0 + 1];
                float d0 = sCoef[320 + f0], d1 = sCoef[320 + f0 + 1];
                float bh0 = sBias[256 + f0], bh1 = sBias[256 + f0 + 1];
                ull acc[2];
#pragma unroll
                for (int jy = 0; jy < 2; jy++) {
                    float s = sS[r0 + jy];
                    acc[jy] = pack2(s * c0 + d0 + bh0, s * c1 + d1 + bh1);
                }
#pragma unroll 4
                for (int ff = 0; ff < 64; ff += 4) {
                    float4 Hq[2];
#pragma unroll
                    for (int jy = 0; jy < 2; jy++) Hq[jy] = *(const float4*)&hrS[(r0 + jy) * 64 + ff];
                    const float* Hp = (const float*)Hq;
#pragma unroll
                    for (int s = 0; s < 4; s++) {
                        ull wv = *(const ull*)&sWh[(ff + s) * 64 + f0];
#pragma unroll
                        for (int jy = 0; jy < 2; jy++) fma2(acc[jy], splat2(Hp[jy * 4 + s]), wv);
                    }
                }
                __syncwarp();
#pragma unroll
                for (int jy = 0; jy < 2; jy++) {
                    float2 a = unpack2(acc[jy]);
                    float ht0 = tanhf(a.x);
                    float ht1 = tanhf(a.y);
                    float2 hv = *(const float2*)&hS[(r0 + jy) * 64 + f0];
                    float hn0 = zz[jy].x * hv.x + (1.0f - zz[jy].x) * ht0;
                    float hn1 = zz[jy].y * hv.y + (1.0f - zz[jy].y) * ht1;
                    *(float2*)&hS[(r0 + jy) * 64 + f0] = make_float2(hn0, hn1);
                    if (t == Tn - 1)
                        *(float2*)&g_h[(bA * Nn + n0 + r0 + jy) * Hn + f0] = make_float2(hn0, hn1);
                }
            }
            // ---- next-step XW ----
            if (t < Tn - 1) {
                __syncthreads();
                ull acc[2] = {0ull, 0ull};
#pragma unroll
                for (int c = 0; c < Wn; c++) {
                    ull wv = *(const ull*)&sWg[c * 64 + f0];
#pragma unroll
                    for (int jy = 0; jy < 2; jy++) fma2(acc[jy], splat2(sIt[(r0 + jy) * 12 + c]), wv);
                }
#pragma unroll 4
                for (int c = 0; c < Hn; c++) {
                    ull wv = *(const ull*)&sWg[(Wn + c) * 64 + f0];
#pragma unroll
                    for (int jy = 0; jy < 2; jy++) fma2(acc[jy], splat2(hS[(r0 + jy) * 64 + c]), wv);
                }
#pragma unroll
                for (int jy = 0; jy < 2; jy++)
                    *(float2*)&g_XW[(bA * Nn + n0 + r0 + jy) * EDn + f0] = unpack2(acc[jy]);
            }
        }
        gsync_b(grp, lgen);
    }
}

// ---------------- final classifier ----------------
__global__ __launch_bounds__(256) void k_cls(const float* __restrict__ cls_w,
                                             const float* __restrict__ cls_b,
                                             float* __restrict__ out) {
    int b = blockIdx.x, tid = threadIdx.x;
    float acc[4] = {0.f, 0.f, 0.f, 0.f};
    for (int i = tid; i < Nn * Hn; i += 256) {
        float hv = g_h[b * Nn * Hn + i];
#pragma unroll
        for (int c = 0; c < 4; c++) acc[c] += hv * cls_w[i * Cn + c];
    }
    __shared__ float red[4][256];
#pragma unroll
    for (int c = 0; c < 4; c++) red[c][tid] = acc[c];
    __syncthreads();
    for (int s = 128; s > 0; s >>= 1) {
        if (tid < s) {
#pragma unroll
            for (int c = 0; c < 4; c++) red[c][tid] += red[c][tid + s];
        }
        __syncthreads();
    }
    if (tid < 4) out[b * Cn + tid] = red[tid][0] + cls_b[tid];
}

// ---------------- launch ----------------
extern "C" void kernel_launch(void* const* d_in, const int* in_sizes, int n_in,
                              void* d_out, int out_size) {
    const float* x        = (const float*)d_in[0];
    const float* ew       = (const float*)d_in[1];
    const float* gconv_w  = (const float*)d_in[2];
    const float* gconv_b  = (const float*)d_in[3];
    const float* w1       = (const float*)d_in[4];
    const float* b1       = (const float*)d_in[5];
    const float* w2       = (const float*)d_in[6];
    const float* b2       = (const float*)d_in[7];
    const float* wz_c     = (const float*)d_in[8];
    const float* bz_c     = (const float*)d_in[9];
    const float* wz_l     = (const float*)d_in[10];
    const float* bz_l     = (const float*)d_in[11];
    const float* wr_c     = (const float*)d_in[12];
    const float* br_c     = (const float*)d_in[13];
    const float* wr_l     = (const float*)d_in[14];
    const float* br_l     = (const float*)d_in[15];
    const float* wh_c     = (const float*)d_in[16];
    const float* bh_c     = (const float*)d_in[17];
    const float* wh_l     = (const float*)d_in[18];
    const float* bh_l     = (const float*)d_in[19];
    const float* cls_w    = (const float*)d_in[20];
    const float* cls_b    = (const float*)d_in[21];
    const int*   eidx     = (const int*)d_in[22];
    float* out = (float*)d_out;

    static int smem_set = 0;
    if (!smem_set) {
        cudaFuncSetAttribute(k_persist, cudaFuncAttributeMaxDynamicSharedMemorySize, SMEM_BYTES);
        smem_set = 1;
    }

    k_zero<<<2048, 256>>>();
    k_build<<<1, 256>>>(eidx, ew);
    k_precoef<<<1, 64>>>(wz_c, wz_l, bz_c, wr_c, wr_l, br_c, wh_c, wh_l, bh_c);
    k_persist<<<NBLK, NT, SMEM_BYTES>>>(x, gconv_w, gconv_b, w1, b1, w2, b2,
                                        bz_l, wz_l, br_l, wr_l, bh_l, wh_l);
    k_cls<<<Bn, 256>>>(cls_w, cls_b, out);
}

// round 17
// speedup vs baseline: 3.4681x; 1.0236x over previous
#include <cuda_runtime.h>
#include <math.h>

#define Bn 16
#define Nn 256
#define Tn 64
#define Wn 12
#define Hn 64
#define EDn 64
#define Sn 5
#define Cn 4
#define En 2048
#define FGn 76   // W + H
#define CAP 64
#define GBLK 9            // blocks per batch group
#define NBLK (Bn * GBLK)  // 144
#define NT 512            // threads per block

typedef unsigned long long ull;

// ---------------- f32x2 packed-FMA helpers (sm_103a FFMA2) ----------------
__device__ __forceinline__ void fma2(ull& d, ull a, ull b) {
    asm("fma.rn.f32x2 %0, %1, %2, %0;" : "+l"(d) : "l"(a), "l"(b));
}
__device__ __forceinline__ ull splat2(float v) {
    ull r; asm("mov.b64 %0, {%1, %1};" : "=l"(r) : "f"(v)); return r;
}
__device__ __forceinline__ ull pack2(float lo, float hi) {
    ull r; asm("mov.b64 %0, {%1, %2};" : "=l"(r) : "f"(lo), "f"(hi)); return r;
}
__device__ __forceinline__ float2 unpack2(ull v) {
    float lo, hi; asm("mov.b64 {%0, %1}, %2;" : "=f"(lo), "=f"(hi) : "l"(v));
    return make_float2(lo, hi);
}
__device__ __forceinline__ float hadd2(ull v) { float2 f = unpack2(v); return f.x + f.y; }

// phase-B pair partition: role -> 4 pairs, each role spans <=4 distinct tiles
__device__ __constant__ signed char c_bi[9][4] = {
    {0,0,0,0}, {1,1,1,2}, {2,3,6,7}, {4,4,4,4}, {5,5,5,6},
    {0,0,1,1}, {0,0,1,1}, {2,2,3,3}, {2,2,3,3}};
__device__ __constant__ signed char c_bj[9][4] = {
    {0,1,2,3}, {1,2,3,3}, {2,3,6,7}, {4,5,6,7}, {5,6,7,7},
    {4,5,4,5}, {6,7,6,7}, {4,5,4,5}, {6,7,6,7}};
__device__ __constant__ signed char c_nload[9] = {4,3,4,4,3,4,4,4,4};
__device__ __constant__ signed char c_tiles[9][4] = {
    {0,1,2,3}, {1,2,3,3}, {2,3,6,7}, {4,5,6,7}, {5,6,7,7},
    {0,1,4,5}, {0,1,6,7}, {2,3,4,5}, {2,3,6,7}};
__device__ __constant__ signed char c_pi[9][4] = {
    {0,0,0,0}, {0,0,0,1}, {0,1,2,3}, {0,0,0,0}, {0,0,0,1},
    {0,0,1,1}, {0,0,1,1}, {0,0,1,1}, {0,0,1,1}};
__device__ __constant__ signed char c_pj[9][4] = {
    {0,1,2,3}, {0,1,2,2}, {0,1,2,3}, {0,1,2,3}, {0,1,2,2},
    {2,3,2,3}, {2,3,2,3}, {2,3,2,3}, {2,3,2,3}};

// ---------------- device scratch ----------------
__device__ float g_dinv_stat[Nn];
__device__ int   g_nbr_cnt[Nn];
__device__ int   g_nbr_idx[Nn * CAP];
__device__ float g_nbr_w[Nn * CAP];
__device__ float g_coef[6 * Hn];
__device__ float g_XW[Bn * Nn * EDn];
__device__ float g_de1[Bn * Nn * EDn];
__device__ float g_de2[Bn * Nn * EDn];
__device__ float g_Eh[(size_t)Bn * Sn * Nn * Nn];
__device__ float g_Msum[(size_t)Bn * Nn * Nn];
__device__ float g_colsum[Bn * Nn];
__device__ float g_h[Bn * Nn * Hn];
__device__ unsigned g_bcount[Bn * 32];
__device__ unsigned g_bgen[Bn * 32];
__device__ unsigned g_deflag[Bn * 64];   // per (batch, role) de-ready flag, 32B apart

// ---------------- smem layout (floats) ----------------
#define OFF_W1   0
#define OFF_W2   4096
#define OFF_WZ   8192
#define OFF_WR   12288
#define OFF_WH   16384
#define OFF_WG   20480          // 4864
#define OFF_COEF 25344          // 384
#define OFF_BIAS 25728          // 384: [b1,b2,bz,br,bh,gconv_b]
#define OFF_H    26112          // 2048 persistent h rows
#define OFF_NBRW 28160          // 2048
#define OFF_NBRI 30208          // 2048 (int view)
#define OFF_NBRC 32256          // 32 (int view)
#define OFF_WK   32288
// phase B: 4 pool slots x (de1,de2) x 32x68 + 4 x tS(32x33) + colbuf(256)
#define DSLOT    4352           // 2 * 2176
#define OFF_TS   (4 * DSLOT)            // 17408 (relative to wk)
#define OFF_CBR  (OFF_TS + 4 * 1056)    // 21632 (relative to wk)
#define WKSZ     (OFF_CBR + 256)        // 21888
#define SMEM_FLOATS (OFF_WK + WKSZ)
#define SMEM_BYTES (SMEM_FLOATS * 4)

// ---------------- per-batch grid barrier (9 arrivals) ----------------
__device__ __forceinline__ void gsync_b(int grp, unsigned& lgen) {
    __syncthreads();
    if (threadIdx.x == 0) {
        unsigned* cnt = &g_bcount[grp * 32];
        unsigned* gen = &g_bgen[grp * 32];
        __threadfence();
        if (atomicAdd(cnt, 1u) == (unsigned)(GBLK - 1)) {
            *cnt = 0u;
            __threadfence();
            atomicAdd(gen, 1u);
        } else {
            while (atomicAdd(gen, 0u) <= lgen) { __nanosleep(20); }
        }
        __threadfence();
    }
    lgen++;
    __syncthreads();
}

// ---------------- setup kernels ----------------
__global__ void k_zero() {
    size_t idx = (size_t)blockIdx.x * blockDim.x + threadIdx.x;
    size_t str = (size_t)gridDim.x * blockDim.x;
    if (idx < Bn * 32) { g_bcount[idx] = 0u; g_bgen[idx] = 0u; }
    if (idx < Bn * 64) g_deflag[idx] = 0u;
    for (size_t i = idx; i < (size_t)Bn * Sn * Nn * Nn; i += str) g_Eh[i] = 0.f;
    for (size_t i = idx; i < (size_t)Bn * Nn * Nn; i += str) g_Msum[i] = 0.f;
    for (size_t i = idx; i < (size_t)Bn * Nn; i += str) g_colsum[i] = 0.f;
}

__global__ void k_build(const int* __restrict__ ei, const float* __restrict__ ew) {
    int j = threadIdx.x;  // 256 threads, 1 block
    float deg = 1.0f;
    for (int e = 0; e < En; e++)
        if (ei[En + e] == j) deg += ew[e];
    g_dinv_stat[j] = 1.0f / sqrtf(deg);
    __syncthreads();
    float dj = g_dinv_stat[j];
    int cnt = 1;
    g_nbr_idx[j * CAP] = j;
    g_nbr_w[j * CAP] = dj * dj;
    for (int e = 0; e < En; e++) {
        if (ei[En + e] == j && cnt < CAP) {
            int s = ei[e];
            g_nbr_idx[j * CAP + cnt] = s;
            g_nbr_w[j * CAP + cnt] = g_dinv_stat[s] * ew[e] * dj;
            cnt++;
        }
    }
    g_nbr_cnt[j] = cnt;
}

__global__ void k_precoef(const float* wz_c, const float* wz_l, const float* bz_c,
                          const float* wr_c, const float* wr_l, const float* br_c,
                          const float* wh_c, const float* wh_l, const float* bh_c) {
    int k = threadIdx.x;  // 64 threads
    float az = 0, cz = 0, ar = 0, cr = 0, ah = 0, ch = 0;
    for (int f = 0; f < Hn; f++) {
        float wzl = wz_l[f * Hn + k], wrl = wr_l[f * Hn + k], whl = wh_l[f * Hn + k];
        az += wz_c[f] * wzl;  cz += bz_c[f] * wzl;
        ar += wr_c[f] * wrl;  cr += br_c[f] * wrl;
        ah += wh_c[f] * whl;  ch += bh_c[f] * whl;
    }
    g_coef[k] = az;        g_coef[64 + k] = cz;
    g_coef[128 + k] = ar;  g_coef[192 + k] = cr;
    g_coef[256 + k] = ah;  g_coef[320 + k] = ch;
}

// ---------------- persistent kernel: whole T-step scan ----------------
__global__ __launch_bounds__(NT, 1) void k_persist(
    const float* __restrict__ x, const float* __restrict__ Wg,
    const float* __restrict__ gconv_b,
    const float* __restrict__ w1, const float* __restrict__ b1,
    const float* __restrict__ w2, const float* __restrict__ b2,
    const float* __restrict__ bz_lf, const float* __restrict__ wz_l,
    const float* __restrict__ br_lf, const float* __restrict__ wr_l,
    const float* __restrict__ bh_lf, const float* __restrict__ wh_l)
{
    extern __shared__ float sm[];
    int tid = threadIdx.x, bid = blockIdx.x;
    int grp = bid / GBLK;          // batch
    int role = bid - grp * GBLK;   // 0..8
    int bA = grp, nT = role;
    bool ac_on = (role < 8);
    unsigned lgen = 0;

    float* sW1 = sm + OFF_W1;
    float* sW2 = sm + OFF_W2;
    float* sWz = sm + OFF_WZ;
    float* sWr = sm + OFF_WR;
    float* sWh = sm + OFF_WH;
    float* sWg = sm + OFF_WG;
    float* sCoef = sm + OFF_COEF;
    float* sBias = sm + OFF_BIAS;
    float* hS = sm + OFF_H;
    float* sNbrW = sm + OFF_NBRW;
    int* sNbrI = (int*)(sm + OFF_NBRI);
    int* sNbrC = (int*)(sm + OFF_NBRC);
    float* wk = sm + OFF_WK;

    // ---- load all weights once ----
    for (int i = tid; i < 4096; i += NT) {
        sW1[i] = w1[i];
        sW2[i] = w2[i];
        int r = i >> 6, c = i & 63;
        sWz[i] = wz_l[(64 + r) * 64 + c];
        sWr[i] = wr_l[(64 + r) * 64 + c];
        sWh[i] = wh_l[(64 + r) * 64 + c];
    }
    for (int i = tid; i < FGn * 64; i += NT) sWg[i] = Wg[i];
    for (int i = tid; i < 384; i += NT) sCoef[i] = g_coef[i];
    if (tid < 64) {
        sBias[tid] = b1[tid];        sBias[64 + tid] = b2[tid];
        sBias[128 + tid] = bz_lf[tid]; sBias[192 + tid] = br_lf[tid];
        sBias[256 + tid] = bh_lf[tid]; sBias[320 + tid] = gconv_b[tid];
    }
    for (int i = tid; i < 2048; i += NT) hS[i] = 0.f;

    if (ac_on) {
        for (int i = tid; i < 32 * CAP; i += NT) {
            sNbrI[i] = g_nbr_idx[nT * 32 * CAP + i];
            sNbrW[i] = g_nbr_w[nT * 32 * CAP + i];
        }
        if (tid < 32) sNbrC[tid] = g_nbr_cnt[nT * 32 + tid];
    }
    __syncthreads();

    int tx = tid & 31, ty = tid >> 5;   // ty 0..15
    int f0 = tx * 2, r0 = ty * 2;       // 2-row register tiles (phases A/C)

    // phase B decomposition: 4 groups of 128 threads, one tile pair each
    int pg = tid >> 7;                  // 0..3
    int gt = tid & 127;
    int btx = gt & 15, bty = gt >> 4;   // 16 x 8 grid: cols {btx,btx+16}, rows {bty+8a}

    // ---- initial XW (t=0, h=0) ----
    if (ac_on) {
        float* sIt = wk;  // [32][12]
        for (int i = tid; i < 384; i += NT) {
            int rr = i / 12, c = i - rr * 12;
            int tt = c - (Wn - 1);
            sIt[i] = (tt >= 0) ? x[(bA * Nn + nT * 32 + rr) * Tn + tt] : 0.f;
        }
        __syncthreads();
        ull acc[2] = {0ull, 0ull};
#pragma unroll
        for (int c = 0; c < Wn; c++) {
            ull wv = *(const ull*)&sWg[c * 64 + f0];
#pragma unroll
            for (int jy = 0; jy < 2; jy++) fma2(acc[jy], splat2(sIt[(r0 + jy) * 12 + c]), wv);
        }
#pragma unroll
        for (int jy = 0; jy < 2; jy++)
            *(float2*)&g_XW[(bA * Nn + nT * 32 + r0 + jy) * EDn + f0] = unpack2(acc[jy]);
    }
    gsync_b(grp, lgen);

    for (int t = 0; t < Tn; t++) {
        int slot = t % Sn;
        float cnt = (float)((t + 1 < Sn) ? (t + 1) : Sn);

        // ================= phase A: df gather + de1/de2 =================
        if (ac_on) {
            float* dfS = wk;  // [32][64]
            {
                int f = tid & 63, jg = tid >> 6;   // jg 0..7
                float gb = sBias[320 + f];
#pragma unroll
                for (int q = 0; q < 4; q++) {
                    int jl = jg + q * 8;
                    int nc = sNbrC[jl];
                    float acc = 0.f;
                    for (int k = 0; k < nc; k++)
                        acc += sNbrW[jl * CAP + k] * g_XW[(bA * Nn + sNbrI[jl * CAP + k]) * EDn + f];
                    dfS[jl * 64 + f] = acc + gb;
                }
            }
            __syncthreads();
            ull a1[2], a2[2];
#pragma unroll
            for (int jy = 0; jy < 2; jy++) { a1[jy] = 0ull; a2[jy] = 0ull; }
#pragma unroll 4
            for (int ff = 0; ff < 64; ff += 4) {
                float4 D[2];
#pragma unroll
                for (int jy = 0; jy < 2; jy++) D[jy] = *(const float4*)&dfS[(r0 + jy) * 64 + ff];
                const float* Dp = (const float*)D;
#pragma unroll
                for (int s = 0; s < 4; s++) {
                    ull w1v = *(const ull*)&sW1[(ff + s) * 64 + f0];
                    ull w2v = *(const ull*)&sW2[(ff + s) * 64 + f0];
#pragma unroll
                    for (int jy = 0; jy < 2; jy++) {
                        ull dv = splat2(Dp[jy * 4 + s]);
                        fma2(a1[jy], dv, w1v);
                        fma2(a2[jy], dv, w2v);
                    }
                }
            }
            {
                float bb10 = sBias[f0], bb11 = sBias[f0 + 1];
                float bb20 = sBias[64 + f0], bb21 = sBias[64 + f0 + 1];
#pragma unroll
                for (int jy = 0; jy < 2; jy++) {
                    int row = (bA * Nn + nT * 32 + r0 + jy) * EDn;
                    float2 v1 = unpack2(a1[jy]);
                    float2 v2 = unpack2(a2[jy]);
                    *(float2*)&g_de1[row + f0] = make_float2(tanhf(v1.x + bb10), tanhf(v1.y + bb11));
                    *(float2*)&g_de2[row + f0] = make_float2(tanhf(v2.x + bb20), tanhf(v2.y + bb21));
                }
            }
            // ---- release: de for this tile is ready ----
            __syncthreads();
            if (tid == 0) {
                __threadfence();
                atomicExch(&g_deflag[bA * 64 + role * 8], (unsigned)(t + 1));
            }
        }

        // ===== phase B: wait for producer flags, then single pass over 4-slot pool =====
        {
            float* cb = wk + OFF_CBR;
            if (tid < 256) cb[tid] = 0.f;
            int nload = c_nload[role];
            // point-to-point acquire: poll the <=4 producer roles' flags in parallel
            if (tid < nload) {
                unsigned* fl = &g_deflag[bA * 64 + ((int)c_tiles[role][tid]) * 8];
                while (atomicAdd(fl, 0u) < (unsigned)(t + 1)) { __nanosleep(20); }
                __threadfence();
            }
            __syncthreads();

            for (int u = tid; u < nload * 1024; u += NT) {
                int slot_ = u >> 10;
                int rem = u & 1023;
                int mat = rem >> 9;
                int w = rem & 511;
                int rr = w >> 4, e4 = (w & 15) << 2;
                int tile = c_tiles[role][slot_];
                const float* src = mat ? g_de2 : g_de1;
                *(float4*)&wk[slot_ * DSLOT + mat * 2176 + rr * 68 + e4] =
                    *(const float4*)&src[(bA * Nn + tile * 32 + rr) * EDn + e4];
            }
            __syncthreads();

            int iT = c_bi[role][pg], jT = c_bj[role][pg];
            bool diag = (iT == jT);
            const float* d1i = wk + c_pi[role][pg] * DSLOT;
            const float* d2i = d1i + 2176;
            const float* d1j = wk + c_pj[role][pg] * DSLOT;
            const float* d2j = d1j + 2176;
            float* tS = wk + OFF_TS + pg * 1056;   // [32][33]

            // 4x2 cells: rows {bty+8a}, cols {btx+16c}
            ull accA[4][2], accB[4][2];
#pragma unroll
            for (int a = 0; a < 4; a++)
#pragma unroll
                for (int c = 0; c < 2; c++) { accA[a][c] = 0ull; accB[a][c] = 0ull; }
#pragma unroll
            for (int e0 = 0; e0 < 64; e0 += 4) {
                ulonglong2 P1[4], P2[4];
#pragma unroll
                for (int a = 0; a < 4; a++) {
                    P1[a] = *(const ulonglong2*)&d1i[(bty + 8 * a) * 68 + e0];
                    P2[a] = *(const ulonglong2*)&d2i[(bty + 8 * a) * 68 + e0];
                }
#pragma unroll
                for (int c = 0; c < 2; c++) {
                    ulonglong2 Q1 = *(const ulonglong2*)&d1j[(btx + 16 * c) * 68 + e0];
                    ulonglong2 Q2 = *(const ulonglong2*)&d2j[(btx + 16 * c) * 68 + e0];
#pragma unroll
                    for (int a = 0; a < 4; a++) {
                        fma2(accA[a][c], P1[a].x, Q2.x);  fma2(accA[a][c], P1[a].y, Q2.y);
                        fma2(accB[a][c], Q1.x, P2[a].x);  fma2(accB[a][c], Q1.y, P2[a].y);
                    }
                }
            }
#pragma unroll
            for (int a = 0; a < 4; a++)
#pragma unroll
                for (int c = 0; c < 2; c++)
                    tS[(bty + 8 * a) * 33 + btx + 16 * c] =
                        tanhf(hadd2(accA[a][c]) - hadd2(accB[a][c]));
            __syncthreads();

            // fused coalesced RMW: per-thread 8-row column strip
            size_t ebase = ((size_t)(bA * Sn + slot) * Nn) * Nn;
            size_t mbase = ((size_t)bA * Nn) * Nn;
            int cc = gt & 31, rg = gt >> 5;   // 4 row-groups x 8 rows
            float* cbg = cb + pg * 64;
            {
                float csum = 0.f;
#pragma unroll
                for (int k = 0; k < 8; k++) {
                    int r = rg * 8 + k;
                    float et = fmaxf(tS[r * 33 + cc], 0.f);
                    size_t eo = ebase + (size_t)(iT * 32 + r) * Nn + jT * 32 + cc;
                    float old = g_Eh[eo];
                    g_Eh[eo] = et;
                    float d = et - old;
                    g_Msum[mbase + (size_t)(iT * 32 + r) * Nn + jT * 32 + cc] += d;
                    csum += d;
                }
                atomicAdd(&cbg[cc], csum);
            }
            if (!diag) {
                float csum = 0.f;
#pragma unroll
                for (int k = 0; k < 8; k++) {
                    int r = rg * 8 + k;                      // mirror row (jT range)
                    float et = fmaxf(-tS[cc * 33 + r], 0.f); // transposed read, conflict-free
                    size_t eo = ebase + (size_t)(jT * 32 + r) * Nn + iT * 32 + cc;
                    float old = g_Eh[eo];
                    g_Eh[eo] = et;
                    float d = et - old;
                    g_Msum[mbase + (size_t)(jT * 32 + r) * Nn + iT * 32 + cc] += d;
                    csum += d;
                }
                atomicAdd(&cbg[32 + cc], csum);
            }
            __syncthreads();
            // merge colbufs to global
            if (tid < 256) {
                int g = tid >> 6, k = tid & 63;
                int iTT = c_bi[role][g], jTT = c_bj[role][g];
                if (k < 32) {
                    atomicAdd(&g_colsum[bA * Nn + jTT * 32 + k], cb[g * 64 + k]);
                } else if (iTT != jTT) {
                    atomicAdd(&g_colsum[bA * Nn + iTT * 32 + (k - 32)], cb[g * 64 + k]);
                }
            }
        }
        gsync_b(grp, lgen);

        // ================= phase C: s-reduction + GRU + next XW =================
        if (ac_on) {
            int n0 = nT * 32;
            float* hrS   = wk;          // [32][64]
            float* dinvS = wk + 2048;   // 256
            float* dxvS  = wk + 2304;   // 256
            float* part  = wk + 2560;   // 512
            float* sS    = wk + 3072;   // 32
            float* sIt   = wk + 3104;   // [32][12]
            float inv_cnt = 1.0f / cnt;

            if (tid < 256) {
                int i = tid;
                float cs = g_colsum[bA * Nn + i];
                float dv = 1.0f / sqrtf(cs * inv_cnt + 1.0f);
                dinvS[i] = dv;
                dxvS[i] = dv * x[(bA * Nn + i) * Tn + t];
            }
            if (t < Tn - 1) {
                for (int i = tid; i < 384; i += NT) {
                    int rr = i / 12, c = i - rr * 12;
                    int tt = t + 1 + c - (Wn - 1);
                    sIt[i] = (tt >= 0) ? x[(bA * Nn + n0 + rr) * Tn + tt] : 0.f;
                }
            }
            __syncthreads();
            {
                int c = tid & 31, g = tid >> 5;   // 16 groups of 16 i's
                float acc = 0.f;
                int ibase = g * 16;
#pragma unroll 8
                for (int k = 0; k < 16; k++) {
                    int i = ibase + k;
                    acc += g_Msum[((size_t)bA * Nn + i) * Nn + n0 + c] * dxvS[i];
                }
                part[g * 32 + c] = acc;
            }
            __syncthreads();
            if (tid < 32) {
                float sraw = 0.f;
#pragma unroll
                for (int g = 0; g < 16; g++) sraw += part[g * 32 + tid];
                int n = n0 + tid;
                float dj = dinvS[n];
                sS[tid] = dj * (sraw * inv_cnt + dj * x[(bA * Nn + n) * Tn + t]);
            }
            __syncthreads();

            float2 zz[2];
            // ---- z gate ----
            {
                float c0 = sCoef[f0], c1 = sCoef[f0 + 1];
                float d0 = sCoef[64 + f0], d1 = sCoef[64 + f0 + 1];
                float bz0 = sBias[128 + f0], bz1 = sBias[128 + f0 + 1];
                ull acc[2];
#pragma unroll
                for (int jy = 0; jy < 2; jy++) {
                    float s = sS[r0 + jy];
                    acc[jy] = pack2(s * c0 + d0 + bz0, s * c1 + d1 + bz1);
                }
#pragma unroll 4
                for (int ff = 0; ff < 64; ff += 4) {
                    float4 Hq[2];
#pragma unroll
                    for (int jy = 0; jy < 2; jy++) Hq[jy] = *(const float4*)&hS[(r0 + jy) * 64 + ff];
                    const float* Hp = (const float*)Hq;
#pragma unroll
                    for (int s = 0; s < 4; s++) {
                        ull wv = *(const ull*)&sWz[(ff + s) * 64 + f0];
#pragma unroll
                        for (int jy = 0; jy < 2; jy++) fma2(acc[jy], splat2(Hp[jy * 4 + s]), wv);
                    }
                }
#pragma unroll
                for (int jy = 0; jy < 2; jy++) {
                    float2 a = unpack2(acc[jy]);
                    zz[jy] = make_float2(1.0f / (1.0f + expf(-a.x)), 1.0f / (1.0f + expf(-a.y)));
                }
            }
            // ---- r gate -> hrS ----
            {
                float c0 = sCoef[128 + f0], c1 = sCoef[128 + f0 + 1];
                float d0 = sCoef[192 + f0], d1 = sCoef[192 + f0 + 1];
                float br0 = sBias[192 + f0], br1 = sBias[192 + f0 + 1];
                ull acc[2];
#pragma unroll
                for (int jy = 0; jy < 2; jy++) {
                    float s = sS[r0 + jy];
                    acc[jy] = pack2(s * c0 + d0 + br0, s * c1 + d1 + br1);
                }
#pragma unroll 4
                for (int ff = 0; ff < 64; ff += 4) {
                    float4 Hq[2];
#pragma unroll
                    for (int jy = 0; jy < 2; jy++) Hq[jy] = *(const float4*)&hS[(r0 + jy) * 64 + ff];
                    const float* Hp = (const float*)Hq;
#pragma unroll
                    for (int s = 0; s < 4; s++) {
                        ull wv = *(const ull*)&sWr[(ff + s) * 64 + f0];
#pragma unroll
                        for (int jy = 0; jy < 2; jy++) fma2(acc[jy], splat2(Hp[jy * 4 + s]), wv);
                    }
                }
#pragma unroll
                for (int jy = 0; jy < 2; jy++) {
                    float2 a = unpack2(acc[jy]);
                    float rv0 = 1.0f / (1.0f + expf(-a.x));
                    float rv1 = 1.0f / (1.0f + expf(-a.y));
                    float2 hv = *(const float2*)&hS[(r0 + jy) * 64 + f0];
                    *(float2*)&hrS[(r0 + jy) * 64 + f0] = make_float2(hv.x * rv0, hv.y * rv1);
                }
            }
            __syncwarp();
            // ---- h candidate + combine (rows r0..r0+1 are warp-private) ----
            {
                float c0 = sCoef[256 + f0], c1 = sCoef[256 + f0 + 1];
                float d0 = sCoef[320 + f0], d1 = sCoef[320 + f0 + 1];
                float bh0 = sBias[256 + f0], bh1 = sBias[256 + f0 + 1];
                ull acc[2];
#pragma unroll
                for (int jy = 0; jy < 2; jy++) {
                    float s = sS[r0 + jy];
                    acc[jy] = pack2(s * c0 + d0 + bh0, s * c1 + d1 + bh1);
                }
#pragma unroll 4
                for (int ff = 0; ff < 64; ff += 4) {
                    float4 Hq[2];
#pragma unroll
                    for (int jy = 0; jy < 2; jy++) Hq[jy] = *(const float4*)&hrS[(r0 + jy) * 64 + ff];
                    const float* Hp = (const float*)Hq;
#pragma unroll
                    for (int s = 0; s < 4; s++) {
                        ull wv = *(const ull*)&sWh[(ff + s) * 64 + f0];
#pragma unroll
                        for (int jy = 0; jy < 2; jy++) fma2(acc[jy], splat2(Hp[jy * 4 + s]), wv);
                    }
                }
                __syncwarp();
#pragma unroll
                for (int jy = 0; jy < 2; jy++) {
                    float2 a = unpack2(acc[jy]);
                    float ht0 = tanhf(a.x);
                    float ht1 = tanhf(a.y);
                    float2 hv = *(const float2*)&hS[(r0 + jy) * 64 + f0];
                    float hn0 = zz[jy].x * hv.x + (1.0f - zz[jy].x) * ht0;
                    float hn1 = zz[jy].y * hv.y + (1.0f - zz[jy].y) * ht1;
                    *(float2*)&hS[(r0 + jy) * 64 + f0] = make_float2(hn0, hn1);
                    if (t == Tn - 1)
                        *(float2*)&g_h[(bA * Nn + n0 + r0 + jy) * Hn + f0] = make_float2(hn0, hn1);
                }
            }
            // ---- next-step XW ----
            if (t < Tn - 1) {
                __syncthreads();
                ull acc[2] = {0ull, 0ull};
#pragma unroll
                for (int c = 0; c < Wn; c++) {
                    ull wv = *(const ull*)&sWg[c * 64 + f0];
#pragma unroll
                    for (int jy = 0; jy < 2; jy++) fma2(acc[jy], splat2(sIt[(r0 + jy) * 12 + c]), wv);
                }
#pragma unroll 4
                for (int c = 0; c < Hn; c++) {
                    ull wv = *(const ull*)&sWg[(Wn + c) * 64 + f0];
#pragma unroll
                    for (int jy = 0; jy < 2; jy++) fma2(acc[jy], splat2(hS[(r0 + jy) * 64 + c]), wv);
                }
#pragma unroll
                for (int jy = 0; jy < 2; jy++)
                    *(float2*)&g_XW[(bA * Nn + n0 + r0 + jy) * EDn + f0] = unpack2(acc[jy]);
            }
        }
        gsync_b(grp, lgen);
    }
}

// ---------------- final classifier ----------------
__global__ __launch_bounds__(256) void k_cls(const float* __restrict__ cls_w,
                                             const float* __restrict__ cls_b,
                                             float* __restrict__ out) {
    int b = blockIdx.x, tid = threadIdx.x;
    float acc[4] = {0.f, 0.f, 0.f, 0.f};
    for (int i = tid; i < Nn * Hn; i += 256) {
        float hv = g_h[b * Nn * Hn + i];
#pragma unroll
        for (int c = 0; c < 4; c++) acc[c] += hv * cls_w[i * Cn + c];
    }
    __shared__ float red[4][256];
#pragma unroll
    for (int c = 0; c < 4; c++) red[c][tid] = acc[c];
    __syncthreads();
    for (int s = 128; s > 0; s >>= 1) {
        if (tid < s) {
#pragma unroll
            for (int c = 0; c < 4; c++) red[c][tid] += red[c][tid + s];
        }
        __syncthreads();
    }
    if (tid < 4) out[b * Cn + tid] = red[tid][0] + cls_b[tid];
}

// ---------------- launch ----------------
extern "C" void kernel_launch(void* const* d_in, const int* in_sizes, int n_in,
                              void* d_out, int out_size) {
    const float* x        = (const float*)d_in[0];
    const float* ew       = (const float*)d_in[1];
    const float* gconv_w  = (const float*)d_in[2];
    const float* gconv_b  = (const float*)d_in[3];
    const float* w1       = (const float*)d_in[4];
    const float* b1       = (const float*)d_in[5];
    const float* w2       = (const float*)d_in[6];
    const float* b2       = (const float*)d_in[7];
    const float* wz_c     = (const float*)d_in[8];
    const float* bz_c     = (const float*)d_in[9];
    const float* wz_l     = (const float*)d_in[10];
    const float* bz_l     = (const float*)d_in[11];
    const float* wr_c     = (const float*)d_in[12];
    const float* br_c     = (const float*)d_in[13];
    const float* wr_l     = (const float*)d_in[14];
    const float* br_l     = (const float*)d_in[15];
    const float* wh_c     = (const float*)d_in[16];
    const float* bh_c     = (const float*)d_in[17];
    const float* wh_l     = (const float*)d_in[18];
    const float* bh_l     = (const float*)d_in[19];
    const float* cls_w    = (const float*)d_in[20];
    const float* cls_b    = (const float*)d_in[21];
    const int*   eidx     = (const int*)d_in[22];
    float* out = (float*)d_out;

    static int smem_set = 0;
    if (!smem_set) {
        cudaFuncSetAttribute(k_persist, cudaFuncAttributeMaxDynamicSharedMemorySize, SMEM_BYTES);
        smem_set = 1;
    }

    k_zero<<<2048, 256>>>();
    k_build<<<1, 256>>>(eidx, ew);
    k_precoef<<<1, 64>>>(wz_c, wz_l, bz_c, wr_c, wr_l, br_c, wh_c, wh_l, bh_c);
    k_persist<<<NBLK, NT, SMEM_BYTES>>>(x, gconv_w, gconv_b, w1, b1, w2, b2,
                                        bz_l, wz_l, br_l, wr_l, bh_l, wh_l);
    k_cls<<<Bn, 256>>>(cls_w, cls_b, out);
}